// round 1
// baseline (speedup 1.0000x reference)
#include <cuda_runtime.h>
#include <math.h>

// ---------------- problem constants ----------------
#define BATCH   4
#define TEXT    64
#define NTOK    321          // TEXT + 1 + NPATCH
#define DIM     1024
#define HEADS   16
#define HD      64
#define MLPD    4096
#define NPATCH  256
#define PCH     768          // 3*16*16
#define TDIM    256
#define NLAYERS 2
#define VOCAB   50000
#define IMG     256
#define MROWS   (BATCH*NTOK) // 1284

// ---------------- scratch (static device globals; no allocation) ----------------
__device__ float g_x  [MROWS*DIM];
__device__ float g_xn [MROWS*DIM];
__device__ float g_q  [MROWS*DIM];
__device__ float g_k  [MROWS*DIM];
__device__ float g_v  [MROWS*DIM];
__device__ float g_o  [MROWS*DIM];
__device__ float g_att[BATCH*HEADS*NTOK*NTOK];   // also reused as patch-embed scratch
__device__ float g_h  [MROWS*MLPD];              // also reused as im2col / final-proj scratch
__device__ float g_temb_raw[BATCH*TDIM];
__device__ float g_t1 [BATCH*DIM];               // silu buffers
__device__ float g_temb[BATCH*DIM];
__device__ float g_mod[BATCH*6*DIM];

// ---------------- embeddings ----------------
__global__ void embed_text_cls_kernel(const int* __restrict__ tokens,
                                      const float* __restrict__ W_tok,
                                      const float* __restrict__ pos_text,
                                      const float* __restrict__ cls_tok) {
    int idx = blockIdx.x * blockDim.x + threadIdx.x;   // B * 65 * DIM
    if (idx >= BATCH * 65 * DIM) return;
    int d = idx % DIM;
    int t = (idx / DIM) % 65;
    int b = idx / (DIM * 65);
    float v;
    if (t < TEXT) {
        int tok = tokens[b * TEXT + t];
        v = W_tok[(long)d * VOCAB + tok] + pos_text[t * DIM + d];
    } else {
        v = cls_tok[d];
    }
    g_x[(b * NTOK + t) * DIM + d] = v;
}

__global__ void im2col_kernel(const float* __restrict__ img) {
    int idx = blockIdx.x * blockDim.x + threadIdx.x;   // B * NPATCH * 768
    if (idx >= BATCH * NPATCH * PCH) return;
    int c = idx % PCH;
    int p = (idx / PCH) % NPATCH;
    int b = idx / (PCH * NPATCH);
    int ch = c / 256;
    int pr = (c / 16) % 16;
    int pc = c % 16;
    int hp = p / 16, wp = p % 16;
    g_h[idx] = img[((b * 3 + ch) * IMG + hp * 16 + pr) * IMG + wp * 16 + pc];
}

__global__ void add_posimg_kernel(const float* __restrict__ pos_img) {
    int idx = blockIdx.x * blockDim.x + threadIdx.x;   // B * NPATCH * DIM
    if (idx >= BATCH * NPATCH * DIM) return;
    int d = idx % DIM;
    int p = (idx / DIM) % NPATCH;
    int b = idx / (DIM * NPATCH);
    g_x[(b * NTOK + 65 + p) * DIM + d] = g_att[idx] + pos_img[p * DIM + d];
}

// ---------------- timestep embedding ----------------
__global__ void temb_raw_kernel(const int* __restrict__ tsteps) {
    int idx = blockIdx.x * blockDim.x + threadIdx.x;   // B * TDIM
    if (idx >= BATCH * TDIM) return;
    int i = idx % TDIM;
    int b = idx / TDIM;
    int j = i & 127;
    float f = expf(-logf(10000.0f) * (float)j / 128.0f);
    float a = (float)tsteps[b] * f;
    g_temb_raw[idx] = (i < 128) ? cosf(a) : sinf(a);
}

__global__ void t1_kernel(const float* __restrict__ W_t1, const float* __restrict__ b_t1) {
    int idx = blockIdx.x * blockDim.x + threadIdx.x;   // B * DIM
    if (idx >= BATCH * DIM) return;
    int d = idx % DIM;
    int b = idx / DIM;
    float s = b_t1[d];
    const float* tr = g_temb_raw + b * TDIM;
    const float* w  = W_t1 + d * TDIM;
    for (int k = 0; k < TDIM; k++) s += tr[k] * w[k];
    g_t1[idx] = s / (1.0f + expf(-s));     // silu
}

__global__ void t2_kernel(const float* __restrict__ W_t2, const float* __restrict__ b_t2) {
    int idx = blockIdx.x * blockDim.x + threadIdx.x;   // B * DIM
    if (idx >= BATCH * DIM) return;
    int d = idx % DIM;
    int b = idx / DIM;
    float s = b_t2[d];
    const float* h = g_t1 + b * DIM;
    const float* w = W_t2 + d * DIM;
    for (int k = 0; k < DIM; k++) s += h[k] * w[k];
    g_temb[idx] = s;
}

__global__ void silu_temb_kernel() {
    int idx = blockIdx.x * blockDim.x + threadIdx.x;   // B * DIM
    if (idx >= BATCH * DIM) return;
    float v = g_temb[idx];
    g_t1[idx] = v / (1.0f + expf(-v));
}

// ---------------- generic SGEMM: C = A @ W^T (+ epilogue) ----------------
// A: MxK row-major, W: NtxK row-major, C: MxNt. Nt % 64 == 0, K % 16 == 0.
// epi 0: C = acc (+ bias[col] if bias)        epi 1: C = gelu_exact(acc)
// epi 2: C[row,col] += gate[(row/NTOK)*6*DIM + gate_ofs + col] * acc
__global__ void sgemm_kernel(const float* __restrict__ A, const float* __restrict__ W,
                             float* __restrict__ C, int M, int Nt, int K,
                             const float* __restrict__ bias,
                             const float* __restrict__ gate, int gate_ofs, int epi) {
    __shared__ float As[16][64];
    __shared__ float Ws[16][64];
    int tid = threadIdx.x;
    int row0 = blockIdx.y * 64, col0 = blockIdx.x * 64;
    int tx = tid & 15, ty = tid >> 4;
    int lr = tid >> 2;              // 0..63
    int lk = (tid & 3) * 4;         // 0,4,8,12
    float acc[4][4];
#pragma unroll
    for (int i = 0; i < 4; i++)
#pragma unroll
        for (int j = 0; j < 4; j++) acc[i][j] = 0.0f;

    for (int k0 = 0; k0 < K; k0 += 16) {
        int arow = row0 + lr;
        if (arow < M) {
            const float* ap = A + (long)arow * K + k0 + lk;
#pragma unroll
            for (int i = 0; i < 4; i++) As[lk + i][lr] = ap[i];
        } else {
#pragma unroll
            for (int i = 0; i < 4; i++) As[lk + i][lr] = 0.0f;
        }
        const float* wp = W + (long)(col0 + lr) * K + k0 + lk;
#pragma unroll
        for (int i = 0; i < 4; i++) Ws[lk + i][lr] = wp[i];
        __syncthreads();
#pragma unroll
        for (int kk = 0; kk < 16; kk++) {
            float a[4], w[4];
#pragma unroll
            for (int i = 0; i < 4; i++) a[i] = As[kk][ty * 4 + i];
#pragma unroll
            for (int j = 0; j < 4; j++) w[j] = Ws[kk][tx * 4 + j];
#pragma unroll
            for (int i = 0; i < 4; i++)
#pragma unroll
                for (int j = 0; j < 4; j++) acc[i][j] += a[i] * w[j];
        }
        __syncthreads();
    }

#pragma unroll
    for (int i = 0; i < 4; i++) {
        int row = row0 + ty * 4 + i;
        if (row >= M) continue;
#pragma unroll
        for (int j = 0; j < 4; j++) {
            int col = col0 + tx * 4 + j;
            float v = acc[i][j];
            if (epi == 0) {
                if (bias) v += bias[col];
                C[(long)row * Nt + col] = v;
            } else if (epi == 1) {
                C[(long)row * Nt + col] = 0.5f * v * (1.0f + erff(v * 0.70710678118654752f));
            } else {
                int b = row / NTOK;
                C[(long)row * Nt + col] += gate[b * 6 * DIM + gate_ofs + col] * v;
            }
        }
    }
}

// ---------------- layernorm (+ optional adaLN modulation) ----------------
__global__ void ln_mod_kernel(const float* __restrict__ x, float* __restrict__ xn,
                              const float* __restrict__ g, const float* __restrict__ beta,
                              const float* __restrict__ mod, int sh_ofs, int sc_ofs) {
    int row = blockIdx.x;               // 0..MROWS-1
    int b = row / NTOK;
    const float* xr = x + (long)row * DIM;
    __shared__ float red[256];
    int tid = threadIdx.x;
    float local[4];
    float s = 0.0f;
#pragma unroll
    for (int i = 0; i < 4; i++) { local[i] = xr[tid + i * 256]; s += local[i]; }
    red[tid] = s; __syncthreads();
    for (int o = 128; o > 0; o >>= 1) { if (tid < o) red[tid] += red[tid + o]; __syncthreads(); }
    float mean = red[0] * (1.0f / DIM);
    __syncthreads();
    float s2 = 0.0f;
#pragma unroll
    for (int i = 0; i < 4; i++) { float d = local[i] - mean; s2 += d * d; }
    red[tid] = s2; __syncthreads();
    for (int o = 128; o > 0; o >>= 1) { if (tid < o) red[tid] += red[tid + o]; __syncthreads(); }
    float inv = rsqrtf(red[0] * (1.0f / DIM) + 1e-5f);
#pragma unroll
    for (int i = 0; i < 4; i++) {
        int d = tid + i * 256;
        float v = (local[i] - mean) * inv * g[d] + beta[d];
        v = v * (1.0f + mod[b * 6 * DIM + sc_ofs + d]) + mod[b * 6 * DIM + sh_ofs + d];
        xn[(long)row * DIM + d] = v;
    }
}

__global__ void final_ln_kernel(const float* __restrict__ g, const float* __restrict__ beta) {
    int p = blockIdx.x % NPATCH;
    int b = blockIdx.x / NPATCH;
    const float* xr = g_x + (long)(b * NTOK + 65 + p) * DIM;
    float* orow = g_xn + (long)blockIdx.x * DIM;
    __shared__ float red[256];
    int tid = threadIdx.x;
    float local[4];
    float s = 0.0f;
#pragma unroll
    for (int i = 0; i < 4; i++) { local[i] = xr[tid + i * 256]; s += local[i]; }
    red[tid] = s; __syncthreads();
    for (int o = 128; o > 0; o >>= 1) { if (tid < o) red[tid] += red[tid + o]; __syncthreads(); }
    float mean = red[0] * (1.0f / DIM);
    __syncthreads();
    float s2 = 0.0f;
#pragma unroll
    for (int i = 0; i < 4; i++) { float d = local[i] - mean; s2 += d * d; }
    red[tid] = s2; __syncthreads();
    for (int o = 128; o > 0; o >>= 1) { if (tid < o) red[tid] += red[tid + o]; __syncthreads(); }
    float inv = rsqrtf(red[0] * (1.0f / DIM) + 1e-5f);
#pragma unroll
    for (int i = 0; i < 4; i++) {
        int d = tid + i * 256;
        orow[d] = (local[i] - mean) * inv * g[d] + beta[d];
    }
}

// ---------------- RoPE (in-place, block-staged so no cross-thread hazard) ----------------
__global__ void rope_kernel() {
    int bi = blockIdx.x;                   // 0 .. 2*MROWS*HEADS
    float* buf = (bi >= MROWS * HEADS) ? g_k : g_q;
    int rh = bi % (MROWS * HEADS);
    int row = rh / HEADS, h = rh % HEADS;
    int n = row % NTOK;
    int i = threadIdx.x;                   // 0..63
    __shared__ float sx[HD];
    float* p = buf + (long)row * DIM + h * HD;
    sx[i] = p[i];
    __syncthreads();
    float inv = powf(10000.0f, -(float)(2 * (i & 31)) / 64.0f);
    float ang = (float)n * inv;
    float cs = cosf(ang), sn = sinf(ang);
    float rot = (i < 32) ? -sx[2 * i + 1] : sx[2 * (i - 32)];
    p[i] = sx[i] * cs + rot * sn;
}

// ---------------- attention ----------------
__global__ void attn_scores_kernel() {
    int blk = blockIdx.x;                  // ((b*HEADS)+h)*NTOK + n
    int n = blk % NTOK;
    int bh = blk / NTOK;
    int h = bh % HEADS;
    int b = bh / HEADS;
    int tid = threadIdx.x;                 // 128 threads
    __shared__ float sq[HD];
    __shared__ float ss[NTOK];
    __shared__ float red[128];
    const float* qrow = g_q + (long)(b * NTOK + n) * DIM + h * HD;
    if (tid < HD) sq[tid] = qrow[tid];
    __syncthreads();
    float lmax = -1e30f;
    for (int m = tid; m < NTOK; m += 128) {
        const float* krow = g_k + (long)(b * NTOK + m) * DIM + h * HD;
        float s = 0.0f;
#pragma unroll 16
        for (int d = 0; d < HD; d++) s += sq[d] * krow[d];
        s *= 0.125f;                       // HD^-0.5
        ss[m] = s;
        lmax = fmaxf(lmax, s);
    }
    red[tid] = lmax; __syncthreads();
    for (int o = 64; o > 0; o >>= 1) { if (tid < o) red[tid] = fmaxf(red[tid], red[tid + o]); __syncthreads(); }
    float gmax = red[0]; __syncthreads();
    float lsum = 0.0f;
    for (int m = tid; m < NTOK; m += 128) {
        float e = __expf(ss[m] - gmax);
        ss[m] = e;
        lsum += e;
    }
    red[tid] = lsum; __syncthreads();
    for (int o = 64; o > 0; o >>= 1) { if (tid < o) red[tid] += red[tid + o]; __syncthreads(); }
    float invsum = 1.0f / red[0];
    float* arow = g_att + (long)blk * NTOK;
    for (int m = tid; m < NTOK; m += 128) arow[m] = ss[m] * invsum;
}

__global__ void attn_av_kernel() {
    int blk = blockIdx.x;                  // ((b*HEADS)+h)*NTOK + n
    int n = blk % NTOK;
    int bh = blk / NTOK;
    int h = bh % HEADS;
    int b = bh / HEADS;
    int tid = threadIdx.x;                 // 64 threads
    __shared__ float satt[NTOK];
    const float* arow = g_att + (long)blk * NTOK;
    for (int m = tid; m < NTOK; m += HD) satt[m] = arow[m];
    __syncthreads();
    const float* vbase = g_v + (long)b * NTOK * DIM + h * HD + tid;
    float acc = 0.0f;
    for (int m = 0; m < NTOK; m++) acc += satt[m] * vbase[(long)m * DIM];
    g_o[(long)(b * NTOK + n) * DIM + h * HD + tid] = acc;
}

// ---------------- output unpatchify ----------------
__global__ void unpatch_kernel(float* __restrict__ out) {
    int idx = blockIdx.x * blockDim.x + threadIdx.x;   // B*3*IMG*IMG
    if (idx >= BATCH * 3 * IMG * IMG) return;
    int c_img = idx % IMG;
    int r_img = (idx / IMG) % IMG;
    int ch = (idx / (IMG * IMG)) % 3;
    int b = idx / (3 * IMG * IMG);
    int hp = r_img / 16, pr = r_img % 16;
    int wp = c_img / 16, pc = c_img % 16;
    out[idx] = g_h[(long)(b * NPATCH + hp * 16 + wp) * PCH + ch * 256 + pr * 16 + pc];
}

// ---------------- host launch ----------------
static float* symaddr(const void* sym) {
    void* p = nullptr;
    cudaGetSymbolAddress(&p, sym);
    return (float*)p;
}

extern "C" void kernel_launch(void* const* d_in, const int* in_sizes, int n_in,
                              void* d_out, int out_size) {
    const float* noisy    = (const float*)d_in[0];
    const int*   tokens   = (const int*)  d_in[1];
    const int*   tsteps   = (const int*)  d_in[2];
    const float* W_tok    = (const float*)d_in[3];
    const float* pos_text = (const float*)d_in[4];
    const float* W_patch  = (const float*)d_in[5];
    const float* pos_img  = (const float*)d_in[6];
    const float* cls_tok  = (const float*)d_in[7];
    const float* W_t1     = (const float*)d_in[8];
    const float* b_t1     = (const float*)d_in[9];
    const float* W_t2     = (const float*)d_in[10];
    const float* b_t2     = (const float*)d_in[11];
    const float* ln1_g    = (const float*)d_in[12];
    const float* ln1_b    = (const float*)d_in[13];
    const float* Wq       = (const float*)d_in[14];
    const float* Wk       = (const float*)d_in[15];
    const float* Wv       = (const float*)d_in[16];
    const float* Wo       = (const float*)d_in[17];
    const float* ln2_g    = (const float*)d_in[18];
    const float* ln2_b    = (const float*)d_in[19];
    const float* Wm1      = (const float*)d_in[20];
    const float* Wm2      = (const float*)d_in[21];
    const float* Wada     = (const float*)d_in[22];
    const float* b_ada    = (const float*)d_in[23];
    const float* fn_g     = (const float*)d_in[24];
    const float* fn_b     = (const float*)d_in[25];
    const float* W_final  = (const float*)d_in[26];
    const float* b_final  = (const float*)d_in[27];
    float* out = (float*)d_out;

    float* p_x   = symaddr(g_x);
    float* p_xn  = symaddr(g_xn);
    float* p_q   = symaddr(g_q);
    float* p_k   = symaddr(g_k);
    float* p_v   = symaddr(g_v);
    float* p_o   = symaddr(g_o);
    float* p_att = symaddr(g_att);
    float* p_h   = symaddr(g_h);
    float* p_t1  = symaddr(g_t1);
    float* p_mod = symaddr(g_mod);

    // ---- embeddings ----
    {
        int n1 = BATCH * 65 * DIM;
        embed_text_cls_kernel<<<(n1 + 255) / 256, 256>>>(tokens, W_tok, pos_text, cls_tok);
        int n2 = BATCH * NPATCH * PCH;
        im2col_kernel<<<(n2 + 255) / 256, 256>>>(noisy);
        // patch projection: (B*NPATCH x 768) @ W_patch^T -> (B*NPATCH x 1024), into g_att scratch
        sgemm_kernel<<<dim3(DIM / 64, (BATCH * NPATCH) / 64), 256>>>(
            p_h, W_patch, p_att, BATCH * NPATCH, DIM, PCH, nullptr, nullptr, 0, 0);
        int n3 = BATCH * NPATCH * DIM;
        add_posimg_kernel<<<(n3 + 255) / 256, 256>>>(pos_img);
    }

    // ---- timestep embedding ----
    temb_raw_kernel<<<(BATCH * TDIM + 255) / 256, 256>>>(tsteps);
    t1_kernel<<<(BATCH * DIM + 255) / 256, 256>>>(W_t1, b_t1);
    t2_kernel<<<(BATCH * DIM + 255) / 256, 256>>>(W_t2, b_t2);
    silu_temb_kernel<<<(BATCH * DIM + 255) / 256, 256>>>();   // g_t1 = silu(t_emb)

    int gy = (MROWS + 63) / 64;   // 21

    for (int l = 0; l < NLAYERS; l++) {
        const float* Wq_l   = Wq   + (long)l * DIM * DIM;
        const float* Wk_l   = Wk   + (long)l * DIM * DIM;
        const float* Wv_l   = Wv   + (long)l * DIM * DIM;
        const float* Wo_l   = Wo   + (long)l * DIM * DIM;
        const float* Wm1_l  = Wm1  + (long)l * MLPD * DIM;
        const float* Wm2_l  = Wm2  + (long)l * DIM * MLPD;
        const float* Wada_l = Wada + (long)l * 6 * DIM * DIM;
        const float* bada_l = b_ada + (long)l * 6 * DIM;

        // adaLN modulation: (B x DIM) @ Wada^T + b_ada -> (B x 6*DIM)
        sgemm_kernel<<<dim3(6 * DIM / 64, 1), 256>>>(
            p_t1, Wada_l, p_mod, BATCH, 6 * DIM, DIM, bada_l, nullptr, 0, 0);

        // LN1 + modulation
        ln_mod_kernel<<<MROWS, 256>>>(p_x, p_xn, ln1_g + l * DIM, ln1_b + l * DIM,
                                      p_mod, 0, DIM);

        // Q, K, V projections
        sgemm_kernel<<<dim3(DIM / 64, gy), 256>>>(p_xn, Wq_l, p_q, MROWS, DIM, DIM, nullptr, nullptr, 0, 0);
        sgemm_kernel<<<dim3(DIM / 64, gy), 256>>>(p_xn, Wk_l, p_k, MROWS, DIM, DIM, nullptr, nullptr, 0, 0);
        sgemm_kernel<<<dim3(DIM / 64, gy), 256>>>(p_xn, Wv_l, p_v, MROWS, DIM, DIM, nullptr, nullptr, 0, 0);

        // RoPE on q and k
        rope_kernel<<<2 * MROWS * HEADS, HD>>>();

        // attention
        attn_scores_kernel<<<BATCH * HEADS * NTOK, 128>>>();
        attn_av_kernel<<<BATCH * HEADS * NTOK, HD>>>();

        // x += g_msa * (o @ Wo^T)
        sgemm_kernel<<<dim3(DIM / 64, gy), 256>>>(p_o, Wo_l, p_x, MROWS, DIM, DIM,
                                                  nullptr, p_mod, 2 * DIM, 2);

        // LN2 + modulation
        ln_mod_kernel<<<MROWS, 256>>>(p_x, p_xn, ln2_g + l * DIM, ln2_b + l * DIM,
                                      p_mod, 3 * DIM, 4 * DIM);

        // MLP: h = gelu(xn2 @ Wm1^T); x += g_mlp * (h @ Wm2^T)
        sgemm_kernel<<<dim3(MLPD / 64, gy), 256>>>(p_xn, Wm1_l, p_h, MROWS, MLPD, DIM,
                                                   nullptr, nullptr, 0, 1);
        sgemm_kernel<<<dim3(DIM / 64, gy), 256>>>(p_h, Wm2_l, p_x, MROWS, DIM, MLPD,
                                                  nullptr, p_mod, 5 * DIM, 2);
    }

    // ---- final head ----
    final_ln_kernel<<<BATCH * NPATCH, 256>>>(fn_g, fn_b);
    sgemm_kernel<<<dim3(PCH / 64, (BATCH * NPATCH) / 64), 256>>>(
        p_xn, W_final, p_h, BATCH * NPATCH, PCH, DIM, b_final, nullptr, 0, 0);
    int n4 = BATCH * 3 * IMG * IMG;
    unpatch_kernel<<<(n4 + 255) / 256, 256>>>(out);
}

// round 2
// speedup vs baseline: 1.4198x; 1.4198x over previous
#include <cuda_runtime.h>
#include <cuda_bf16.h>
#include <math.h>

// ---------------- problem constants ----------------
#define BATCH   4
#define TEXT    64
#define NTOK    321          // TEXT + 1 + NPATCH
#define DIM     1024
#define HEADS   16
#define HD      64
#define MLPD    4096
#define NPATCH  256
#define PCH     768          // 3*16*16
#define TDIM    256
#define NLAYERS 2
#define VOCAB   50000
#define IMG     256
#define MROWS   (BATCH*NTOK) // 1284

// ---------------- scratch (static device globals; no allocation) ----------------
__device__ float g_x  [MROWS*DIM];
__device__ float g_xn [MROWS*DIM];
__device__ float g_q  [MROWS*DIM];
__device__ float g_k  [MROWS*DIM];
__device__ float g_v  [MROWS*DIM];
__device__ float g_o  [MROWS*DIM];
__device__ float g_att[BATCH*HEADS*NTOK*NTOK];   // also reused as patch-embed scratch
__device__ float g_h  [MROWS*MLPD];              // also reused as im2col / final-proj scratch
__device__ float g_temb_raw[BATCH*TDIM];
__device__ float g_t1 [BATCH*DIM];               // silu buffers
__device__ float g_temb[BATCH*DIM];
__device__ float g_mod[BATCH*6*DIM];

// ---------------- embeddings ----------------
__global__ void embed_text_cls_kernel(const int* __restrict__ tokens,
                                      const float* __restrict__ W_tok,
                                      const float* __restrict__ pos_text,
                                      const float* __restrict__ cls_tok) {
    int idx = blockIdx.x * blockDim.x + threadIdx.x;   // B * 65 * DIM
    if (idx >= BATCH * 65 * DIM) return;
    int d = idx % DIM;
    int t = (idx / DIM) % 65;
    int b = idx / (DIM * 65);
    float v;
    if (t < TEXT) {
        int tok = tokens[b * TEXT + t];
        v = W_tok[(long)d * VOCAB + tok] + pos_text[t * DIM + d];
    } else {
        v = cls_tok[d];
    }
    g_x[(b * NTOK + t) * DIM + d] = v;
}

__global__ void im2col_kernel(const float* __restrict__ img) {
    int idx = blockIdx.x * blockDim.x + threadIdx.x;   // B * NPATCH * 768
    if (idx >= BATCH * NPATCH * PCH) return;
    int c = idx % PCH;
    int p = (idx / PCH) % NPATCH;
    int b = idx / (PCH * NPATCH);
    int ch = c / 256;
    int pr = (c / 16) % 16;
    int pc = c % 16;
    int hp = p / 16, wp = p % 16;
    g_h[idx] = img[((b * 3 + ch) * IMG + hp * 16 + pr) * IMG + wp * 16 + pc];
}

__global__ void add_posimg_kernel(const float* __restrict__ pos_img) {
    int idx = blockIdx.x * blockDim.x + threadIdx.x;   // B * NPATCH * DIM
    if (idx >= BATCH * NPATCH * DIM) return;
    int d = idx % DIM;
    int p = (idx / DIM) % NPATCH;
    int b = idx / (DIM * NPATCH);
    g_x[(b * NTOK + 65 + p) * DIM + d] = g_att[idx] + pos_img[p * DIM + d];
}

// ---------------- timestep embedding ----------------
__global__ void temb_raw_kernel(const int* __restrict__ tsteps) {
    int idx = blockIdx.x * blockDim.x + threadIdx.x;   // B * TDIM
    if (idx >= BATCH * TDIM) return;
    int i = idx % TDIM;
    int b = idx / TDIM;
    int j = i & 127;
    float f = expf(-logf(10000.0f) * (float)j / 128.0f);
    float a = (float)tsteps[b] * f;
    g_temb_raw[idx] = (i < 128) ? cosf(a) : sinf(a);
}

__global__ void t1_kernel(const float* __restrict__ W_t1, const float* __restrict__ b_t1) {
    int idx = blockIdx.x * blockDim.x + threadIdx.x;   // B * DIM
    if (idx >= BATCH * DIM) return;
    int d = idx % DIM;
    int b = idx / DIM;
    float s = b_t1[d];
    const float* tr = g_temb_raw + b * TDIM;
    const float* w  = W_t1 + d * TDIM;
    for (int k = 0; k < TDIM; k++) s += tr[k] * w[k];
    g_t1[idx] = s / (1.0f + expf(-s));     // silu
}

__global__ void t2_kernel(const float* __restrict__ W_t2, const float* __restrict__ b_t2) {
    int idx = blockIdx.x * blockDim.x + threadIdx.x;   // B * DIM
    if (idx >= BATCH * DIM) return;
    int d = idx % DIM;
    int b = idx / DIM;
    float s = b_t2[d];
    const float* h = g_t1 + b * DIM;
    const float* w = W_t2 + d * DIM;
    for (int k = 0; k < DIM; k++) s += h[k] * w[k];
    g_temb[idx] = s;
}

__global__ void silu_temb_kernel() {
    int idx = blockIdx.x * blockDim.x + threadIdx.x;   // B * DIM
    if (idx >= BATCH * DIM) return;
    float v = g_temb[idx];
    g_t1[idx] = v / (1.0f + expf(-v));
}

// ---------------- scalar SGEMM (small M cases: adaLN) ----------------
__global__ void sgemm_kernel(const float* __restrict__ A, const float* __restrict__ W,
                             float* __restrict__ C, int M, int Nt, int K,
                             const float* __restrict__ bias,
                             const float* __restrict__ gate, int gate_ofs, int epi) {
    __shared__ float As[16][64];
    __shared__ float Ws[16][64];
    int tid = threadIdx.x;
    int row0 = blockIdx.y * 64, col0 = blockIdx.x * 64;
    int tx = tid & 15, ty = tid >> 4;
    int lr = tid >> 2;
    int lk = (tid & 3) * 4;
    float acc[4][4];
#pragma unroll
    for (int i = 0; i < 4; i++)
#pragma unroll
        for (int j = 0; j < 4; j++) acc[i][j] = 0.0f;

    for (int k0 = 0; k0 < K; k0 += 16) {
        int arow = row0 + lr;
        if (arow < M) {
            const float* ap = A + (long)arow * K + k0 + lk;
#pragma unroll
            for (int i = 0; i < 4; i++) As[lk + i][lr] = ap[i];
        } else {
#pragma unroll
            for (int i = 0; i < 4; i++) As[lk + i][lr] = 0.0f;
        }
        const float* wp = W + (long)(col0 + lr) * K + k0 + lk;
#pragma unroll
        for (int i = 0; i < 4; i++) Ws[lk + i][lr] = wp[i];
        __syncthreads();
#pragma unroll
        for (int kk = 0; kk < 16; kk++) {
            float a[4], w[4];
#pragma unroll
            for (int i = 0; i < 4; i++) a[i] = As[kk][ty * 4 + i];
#pragma unroll
            for (int j = 0; j < 4; j++) w[j] = Ws[kk][tx * 4 + j];
#pragma unroll
            for (int i = 0; i < 4; i++)
#pragma unroll
                for (int j = 0; j < 4; j++) acc[i][j] += a[i] * w[j];
        }
        __syncthreads();
    }

#pragma unroll
    for (int i = 0; i < 4; i++) {
        int row = row0 + ty * 4 + i;
        if (row >= M) continue;
#pragma unroll
        for (int j = 0; j < 4; j++) {
            int col = col0 + tx * 4 + j;
            float v = acc[i][j];
            if (epi == 0) {
                if (bias) v += bias[col];
                C[(long)row * Nt + col] = v;
            } else if (epi == 1) {
                C[(long)row * Nt + col] = 0.5f * v * (1.0f + erff(v * 0.70710678118654752f));
            } else {
                int b = row / NTOK;
                C[(long)row * Nt + col] += gate[b * 6 * DIM + gate_ofs + col] * v;
            }
        }
    }
}

// ---------------- tensor-core GEMM: C = A @ W^T via bf16x3 split ----------------
// A: MxK fp32 row-major; W: NtxK fp32 row-major. Requires Nt%128==0, K%32==0.
// Block tile 64x128x32; 8 warps (2x4), warp tile 32x32 (2x4 m16n8 microtiles).
// Split: a = hi(a)+lo(a); acc += ah*bh + ah*bl + al*bh (fp32 accumulate).
#define SMP 17   // padded row stride in u32 (16 bf16-pairs + 1 pad)

__device__ __forceinline__ void pack_hilo(float v0, float v1, unsigned& hi, unsigned& lo) {
    __nv_bfloat16 h0 = __float2bfloat16_rn(v0);
    __nv_bfloat16 h1 = __float2bfloat16_rn(v1);
    __nv_bfloat16 l0 = __float2bfloat16_rn(v0 - __bfloat162float(h0));
    __nv_bfloat16 l1 = __float2bfloat16_rn(v1 - __bfloat162float(h1));
    hi = (unsigned)__bfloat16_as_ushort(h0) | ((unsigned)__bfloat16_as_ushort(h1) << 16);
    lo = (unsigned)__bfloat16_as_ushort(l0) | ((unsigned)__bfloat16_as_ushort(l1) << 16);
}

__device__ __forceinline__ void mma16816(float* c, const unsigned* a, const unsigned* b) {
    asm volatile(
        "mma.sync.aligned.m16n8k16.row.col.f32.bf16.bf16.f32 "
        "{%0,%1,%2,%3}, {%4,%5,%6,%7}, {%8,%9}, {%0,%1,%2,%3};\n"
        : "+f"(c[0]), "+f"(c[1]), "+f"(c[2]), "+f"(c[3])
        : "r"(a[0]), "r"(a[1]), "r"(a[2]), "r"(a[3]), "r"(b[0]), "r"(b[1]));
}

__global__ __launch_bounds__(256) void mma_gemm_kernel(
        const float* __restrict__ A, const float* __restrict__ W,
        float* __restrict__ C, int M, int Nt, int K,
        const float* __restrict__ bias,
        const float* __restrict__ gate, int gate_ofs, int epi) {
    __shared__ unsigned As_hi[64 * SMP];
    __shared__ unsigned As_lo[64 * SMP];
    __shared__ unsigned Ws_hi[128 * SMP];
    __shared__ unsigned Ws_lo[128 * SMP];

    int tid  = threadIdx.x;
    int lane = tid & 31;
    int warp = tid >> 5;
    int wm = warp >> 2;        // 0..1  (32 rows each)
    int wn = warp & 3;         // 0..3  (32 cols each)
    int row0 = blockIdx.y * 64;
    int col0 = blockIdx.x * 128;

    float acc[2][4][4];
#pragma unroll
    for (int i = 0; i < 2; i++)
#pragma unroll
        for (int j = 0; j < 4; j++)
#pragma unroll
            for (int t = 0; t < 4; t++) acc[i][j][t] = 0.0f;

    for (int k0 = 0; k0 < K; k0 += 32) {
        // ---- stage A (64x32) ----
#pragma unroll
        for (int i = 0; i < 2; i++) {
            int f = tid + i * 256;             // float4 index, 512 total
            int r = f >> 3;
            int kq = (f & 7) * 4;
            float4 v = make_float4(0.f, 0.f, 0.f, 0.f);
            int grow = row0 + r;
            if (grow < M) v = *(const float4*)(A + (long)grow * K + k0 + kq);
            unsigned h0, l0, h1, l1;
            pack_hilo(v.x, v.y, h0, l0);
            pack_hilo(v.z, v.w, h1, l1);
            int w = r * SMP + (kq >> 1);
            As_hi[w] = h0; As_hi[w + 1] = h1;
            As_lo[w] = l0; As_lo[w + 1] = l1;
        }
        // ---- stage W (128x32) ----
#pragma unroll
        for (int i = 0; i < 4; i++) {
            int f = tid + i * 256;             // 1024 total
            int r = f >> 3;
            int kq = (f & 7) * 4;
            float4 v = *(const float4*)(W + (long)(col0 + r) * K + k0 + kq);
            unsigned h0, l0, h1, l1;
            pack_hilo(v.x, v.y, h0, l0);
            pack_hilo(v.z, v.w, h1, l1);
            int w = r * SMP + (kq >> 1);
            Ws_hi[w] = h0; Ws_hi[w + 1] = h1;
            Ws_lo[w] = l0; Ws_lo[w + 1] = l1;
        }
        __syncthreads();

#pragma unroll
        for (int s = 0; s < 2; s++) {          // two k16 steps
            int cofs = s * 8 + (lane & 3);
            unsigned ah[2][4], al[2][4];
#pragma unroll
            for (int mt = 0; mt < 2; mt++) {
                int r = wm * 32 + mt * 16 + (lane >> 2);
                ah[mt][0] = As_hi[r * SMP + cofs];
                ah[mt][1] = As_hi[(r + 8) * SMP + cofs];
                ah[mt][2] = As_hi[r * SMP + cofs + 4];
                ah[mt][3] = As_hi[(r + 8) * SMP + cofs + 4];
                al[mt][0] = As_lo[r * SMP + cofs];
                al[mt][1] = As_lo[(r + 8) * SMP + cofs];
                al[mt][2] = As_lo[r * SMP + cofs + 4];
                al[mt][3] = As_lo[(r + 8) * SMP + cofs + 4];
            }
            unsigned bh[4][2], bl[4][2];
#pragma unroll
            for (int nt = 0; nt < 4; nt++) {
                int n = wn * 32 + nt * 8 + (lane >> 2);
                bh[nt][0] = Ws_hi[n * SMP + cofs];
                bh[nt][1] = Ws_hi[n * SMP + cofs + 4];
                bl[nt][0] = Ws_lo[n * SMP + cofs];
                bl[nt][1] = Ws_lo[n * SMP + cofs + 4];
            }
#pragma unroll
            for (int mt = 0; mt < 2; mt++)
#pragma unroll
                for (int nt = 0; nt < 4; nt++) {
                    mma16816(acc[mt][nt], ah[mt], bh[nt]);
                    mma16816(acc[mt][nt], ah[mt], bl[nt]);
                    mma16816(acc[mt][nt], al[mt], bh[nt]);
                }
        }
        __syncthreads();
    }

    // ---- epilogue ----
#pragma unroll
    for (int mt = 0; mt < 2; mt++) {
#pragma unroll
        for (int nt = 0; nt < 4; nt++) {
#pragma unroll
            for (int half = 0; half < 2; half++) {
                int row = row0 + wm * 32 + mt * 16 + (lane >> 2) + half * 8;
                if (row >= M) continue;
#pragma unroll
                for (int jj = 0; jj < 2; jj++) {
                    int col = col0 + wn * 32 + nt * 8 + (lane & 3) * 2 + jj;
                    float v = acc[mt][nt][half * 2 + jj];
                    if (epi == 0) {
                        if (bias) v += bias[col];
                        C[(long)row * Nt + col] = v;
                    } else if (epi == 1) {
                        C[(long)row * Nt + col] = 0.5f * v * (1.0f + erff(v * 0.70710678118654752f));
                    } else {
                        int b = row / NTOK;
                        C[(long)row * Nt + col] += gate[b * 6 * DIM + gate_ofs + col] * v;
                    }
                }
            }
        }
    }
}

// ---------------- layernorm (+ optional adaLN modulation) ----------------
__global__ void ln_mod_kernel(const float* __restrict__ x, float* __restrict__ xn,
                              const float* __restrict__ g, const float* __restrict__ beta,
                              const float* __restrict__ mod, int sh_ofs, int sc_ofs) {
    int row = blockIdx.x;
    int b = row / NTOK;
    const float* xr = x + (long)row * DIM;
    __shared__ float red[256];
    int tid = threadIdx.x;
    float local[4];
    float s = 0.0f;
#pragma unroll
    for (int i = 0; i < 4; i++) { local[i] = xr[tid + i * 256]; s += local[i]; }
    red[tid] = s; __syncthreads();
    for (int o = 128; o > 0; o >>= 1) { if (tid < o) red[tid] += red[tid + o]; __syncthreads(); }
    float mean = red[0] * (1.0f / DIM);
    __syncthreads();
    float s2 = 0.0f;
#pragma unroll
    for (int i = 0; i < 4; i++) { float d = local[i] - mean; s2 += d * d; }
    red[tid] = s2; __syncthreads();
    for (int o = 128; o > 0; o >>= 1) { if (tid < o) red[tid] += red[tid + o]; __syncthreads(); }
    float inv = rsqrtf(red[0] * (1.0f / DIM) + 1e-5f);
#pragma unroll
    for (int i = 0; i < 4; i++) {
        int d = tid + i * 256;
        float v = (local[i] - mean) * inv * g[d] + beta[d];
        v = v * (1.0f + mod[b * 6 * DIM + sc_ofs + d]) + mod[b * 6 * DIM + sh_ofs + d];
        xn[(long)row * DIM + d] = v;
    }
}

__global__ void final_ln_kernel(const float* __restrict__ g, const float* __restrict__ beta) {
    int p = blockIdx.x % NPATCH;
    int b = blockIdx.x / NPATCH;
    const float* xr = g_x + (long)(b * NTOK + 65 + p) * DIM;
    float* orow = g_xn + (long)blockIdx.x * DIM;
    __shared__ float red[256];
    int tid = threadIdx.x;
    float local[4];
    float s = 0.0f;
#pragma unroll
    for (int i = 0; i < 4; i++) { local[i] = xr[tid + i * 256]; s += local[i]; }
    red[tid] = s; __syncthreads();
    for (int o = 128; o > 0; o >>= 1) { if (tid < o) red[tid] += red[tid + o]; __syncthreads(); }
    float mean = red[0] * (1.0f / DIM);
    __syncthreads();
    float s2 = 0.0f;
#pragma unroll
    for (int i = 0; i < 4; i++) { float d = local[i] - mean; s2 += d * d; }
    red[tid] = s2; __syncthreads();
    for (int o = 128; o > 0; o >>= 1) { if (tid < o) red[tid] += red[tid + o]; __syncthreads(); }
    float inv = rsqrtf(red[0] * (1.0f / DIM) + 1e-5f);
#pragma unroll
    for (int i = 0; i < 4; i++) {
        int d = tid + i * 256;
        orow[d] = (local[i] - mean) * inv * g[d] + beta[d];
    }
}

// ---------------- RoPE ----------------
__global__ void rope_kernel() {
    int bi = blockIdx.x;
    float* buf = (bi >= MROWS * HEADS) ? g_k : g_q;
    int rh = bi % (MROWS * HEADS);
    int row = rh / HEADS, h = rh % HEADS;
    int n = row % NTOK;
    int i = threadIdx.x;
    __shared__ float sx[HD];
    float* p = buf + (long)row * DIM + h * HD;
    sx[i] = p[i];
    __syncthreads();
    float inv = powf(10000.0f, -(float)(2 * (i & 31)) / 64.0f);
    float ang = (float)n * inv;
    float cs = cosf(ang), sn = sinf(ang);
    float rot = (i < 32) ? -sx[2 * i + 1] : sx[2 * (i - 32)];
    p[i] = sx[i] * cs + rot * sn;
}

// ---------------- attention ----------------
__global__ void attn_scores_kernel() {
    int blk = blockIdx.x;
    int n = blk % NTOK;
    int bh = blk / NTOK;
    int h = bh % HEADS;
    int b = bh / HEADS;
    int tid = threadIdx.x;
    __shared__ float sq[HD];
    __shared__ float ss[NTOK];
    __shared__ float red[128];
    const float* qrow = g_q + (long)(b * NTOK + n) * DIM + h * HD;
    if (tid < HD) sq[tid] = qrow[tid];
    __syncthreads();
    float lmax = -1e30f;
    for (int m = tid; m < NTOK; m += 128) {
        const float* krow = g_k + (long)(b * NTOK + m) * DIM + h * HD;
        float s = 0.0f;
#pragma unroll 16
        for (int d = 0; d < HD; d++) s += sq[d] * krow[d];
        s *= 0.125f;
        ss[m] = s;
        lmax = fmaxf(lmax, s);
    }
    red[tid] = lmax; __syncthreads();
    for (int o = 64; o > 0; o >>= 1) { if (tid < o) red[tid] = fmaxf(red[tid], red[tid + o]); __syncthreads(); }
    float gmax = red[0]; __syncthreads();
    float lsum = 0.0f;
    for (int m = tid; m < NTOK; m += 128) {
        float e = __expf(ss[m] - gmax);
        ss[m] = e;
        lsum += e;
    }
    red[tid] = lsum; __syncthreads();
    for (int o = 64; o > 0; o >>= 1) { if (tid < o) red[tid] += red[tid + o]; __syncthreads(); }
    float invsum = 1.0f / red[0];
    float* arow = g_att + (long)blk * NTOK;
    for (int m = tid; m < NTOK; m += 128) arow[m] = ss[m] * invsum;
}

__global__ void attn_av_kernel() {
    int blk = blockIdx.x;
    int n = blk % NTOK;
    int bh = blk / NTOK;
    int h = bh % HEADS;
    int b = bh / HEADS;
    int tid = threadIdx.x;
    __shared__ float satt[NTOK];
    const float* arow = g_att + (long)blk * NTOK;
    for (int m = tid; m < NTOK; m += HD) satt[m] = arow[m];
    __syncthreads();
    const float* vbase = g_v + (long)b * NTOK * DIM + h * HD + tid;
    float acc = 0.0f;
    for (int m = 0; m < NTOK; m++) acc += satt[m] * vbase[(long)m * DIM];
    g_o[(long)(b * NTOK + n) * DIM + h * HD + tid] = acc;
}

// ---------------- output unpatchify ----------------
__global__ void unpatch_kernel(float* __restrict__ out) {
    int idx = blockIdx.x * blockDim.x + threadIdx.x;
    if (idx >= BATCH * 3 * IMG * IMG) return;
    int c_img = idx % IMG;
    int r_img = (idx / IMG) % IMG;
    int ch = (idx / (IMG * IMG)) % 3;
    int b = idx / (3 * IMG * IMG);
    int hp = r_img / 16, pr = r_img % 16;
    int wp = c_img / 16, pc = c_img % 16;
    out[idx] = g_h[(long)(b * NPATCH + hp * 16 + wp) * PCH + ch * 256 + pr * 16 + pc];
}

// ---------------- host launch ----------------
static float* symaddr(const void* sym) {
    void* p = nullptr;
    cudaGetSymbolAddress(&p, sym);
    return (float*)p;
}

extern "C" void kernel_launch(void* const* d_in, const int* in_sizes, int n_in,
                              void* d_out, int out_size) {
    const float* noisy    = (const float*)d_in[0];
    const int*   tokens   = (const int*)  d_in[1];
    const int*   tsteps   = (const int*)  d_in[2];
    const float* W_tok    = (const float*)d_in[3];
    const float* pos_text = (const float*)d_in[4];
    const float* W_patch  = (const float*)d_in[5];
    const float* pos_img  = (const float*)d_in[6];
    const float* cls_tok  = (const float*)d_in[7];
    const float* W_t1     = (const float*)d_in[8];
    const float* b_t1     = (const float*)d_in[9];
    const float* W_t2     = (const float*)d_in[10];
    const float* b_t2     = (const float*)d_in[11];
    const float* ln1_g    = (const float*)d_in[12];
    const float* ln1_b    = (const float*)d_in[13];
    const float* Wq       = (const float*)d_in[14];
    const float* Wk       = (const float*)d_in[15];
    const float* Wv       = (const float*)d_in[16];
    const float* Wo       = (const float*)d_in[17];
    const float* ln2_g    = (const float*)d_in[18];
    const float* ln2_b    = (const float*)d_in[19];
    const float* Wm1      = (const float*)d_in[20];
    const float* Wm2      = (const float*)d_in[21];
    const float* Wada     = (const float*)d_in[22];
    const float* b_ada    = (const float*)d_in[23];
    const float* fn_g     = (const float*)d_in[24];
    const float* fn_b     = (const float*)d_in[25];
    const float* W_final  = (const float*)d_in[26];
    const float* b_final  = (const float*)d_in[27];
    float* out = (float*)d_out;

    float* p_x   = symaddr(g_x);
    float* p_xn  = symaddr(g_xn);
    float* p_q   = symaddr(g_q);
    float* p_k   = symaddr(g_k);
    float* p_v   = symaddr(g_v);
    float* p_o   = symaddr(g_o);
    float* p_att = symaddr(g_att);
    float* p_h   = symaddr(g_h);
    float* p_t1  = symaddr(g_t1);
    float* p_mod = symaddr(g_mod);

    // ---- embeddings ----
    {
        int n1 = BATCH * 65 * DIM;
        embed_text_cls_kernel<<<(n1 + 255) / 256, 256>>>(tokens, W_tok, pos_text, cls_tok);
        int n2 = BATCH * NPATCH * PCH;
        im2col_kernel<<<(n2 + 255) / 256, 256>>>(noisy);
        mma_gemm_kernel<<<dim3(DIM / 128, (BATCH * NPATCH) / 64), 256>>>(
            p_h, W_patch, p_att, BATCH * NPATCH, DIM, PCH, nullptr, nullptr, 0, 0);
        int n3 = BATCH * NPATCH * DIM;
        add_posimg_kernel<<<(n3 + 255) / 256, 256>>>(pos_img);
    }

    // ---- timestep embedding ----
    temb_raw_kernel<<<(BATCH * TDIM + 255) / 256, 256>>>(tsteps);
    t1_kernel<<<(BATCH * DIM + 255) / 256, 256>>>(W_t1, b_t1);
    t2_kernel<<<(BATCH * DIM + 255) / 256, 256>>>(W_t2, b_t2);
    silu_temb_kernel<<<(BATCH * DIM + 255) / 256, 256>>>();

    int gy = (MROWS + 63) / 64;   // 21

    for (int l = 0; l < NLAYERS; l++) {
        const float* Wq_l   = Wq   + (long)l * DIM * DIM;
        const float* Wk_l   = Wk   + (long)l * DIM * DIM;
        const float* Wv_l   = Wv   + (long)l * DIM * DIM;
        const float* Wo_l   = Wo   + (long)l * DIM * DIM;
        const float* Wm1_l  = Wm1  + (long)l * MLPD * DIM;
        const float* Wm2_l  = Wm2  + (long)l * DIM * MLPD;
        const float* Wada_l = Wada + (long)l * 6 * DIM * DIM;
        const float* bada_l = b_ada + (long)l * 6 * DIM;

        // adaLN modulation: (B x DIM) @ Wada^T + b_ada -> (B x 6*DIM)  [tiny M: scalar]
        sgemm_kernel<<<dim3(6 * DIM / 64, 1), 256>>>(
            p_t1, Wada_l, p_mod, BATCH, 6 * DIM, DIM, bada_l, nullptr, 0, 0);

        // LN1 + modulation
        ln_mod_kernel<<<MROWS, 256>>>(p_x, p_xn, ln1_g + l * DIM, ln1_b + l * DIM,
                                      p_mod, 0, DIM);

        // Q, K, V projections (tensor core)
        mma_gemm_kernel<<<dim3(DIM / 128, gy), 256>>>(p_xn, Wq_l, p_q, MROWS, DIM, DIM, nullptr, nullptr, 0, 0);
        mma_gemm_kernel<<<dim3(DIM / 128, gy), 256>>>(p_xn, Wk_l, p_k, MROWS, DIM, DIM, nullptr, nullptr, 0, 0);
        mma_gemm_kernel<<<dim3(DIM / 128, gy), 256>>>(p_xn, Wv_l, p_v, MROWS, DIM, DIM, nullptr, nullptr, 0, 0);

        // RoPE on q and k
        rope_kernel<<<2 * MROWS * HEADS, HD>>>();

        // attention
        attn_scores_kernel<<<BATCH * HEADS * NTOK, 128>>>();
        attn_av_kernel<<<BATCH * HEADS * NTOK, HD>>>();

        // x += g_msa * (o @ Wo^T)
        mma_gemm_kernel<<<dim3(DIM / 128, gy), 256>>>(p_o, Wo_l, p_x, MROWS, DIM, DIM,
                                                      nullptr, p_mod, 2 * DIM, 2);

        // LN2 + modulation
        ln_mod_kernel<<<MROWS, 256>>>(p_x, p_xn, ln2_g + l * DIM, ln2_b + l * DIM,
                                      p_mod, 3 * DIM, 4 * DIM);

        // MLP (tensor core)
        mma_gemm_kernel<<<dim3(MLPD / 128, gy), 256>>>(p_xn, Wm1_l, p_h, MROWS, MLPD, DIM,
                                                       nullptr, nullptr, 0, 1);
        mma_gemm_kernel<<<dim3(DIM / 128, gy), 256>>>(p_h, Wm2_l, p_x, MROWS, DIM, MLPD,
                                                      nullptr, p_mod, 5 * DIM, 2);
    }

    // ---- final head ----
    final_ln_kernel<<<BATCH * NPATCH, 256>>>(fn_g, fn_b);
    mma_gemm_kernel<<<dim3(PCH / 128, (BATCH * NPATCH) / 64), 256>>>(
        p_xn, W_final, p_h, BATCH * NPATCH, PCH, DIM, b_final, nullptr, 0, 0);
    int n4 = BATCH * 3 * IMG * IMG;
    unpatch_kernel<<<(n4 + 255) / 256, 256>>>(out);
}

// round 3
// speedup vs baseline: 1.5382x; 1.0834x over previous
#include <cuda_runtime.h>
#include <cuda_bf16.h>
#include <math.h>

// ---------------- problem constants ----------------
#define BATCH   4
#define TEXT    64
#define NTOK    321
#define DIM     1024
#define HEADS   16
#define HD      64
#define MLPD    4096
#define NPATCH  256
#define PCH     768
#define TDIM    256
#define NLAYERS 2
#define VOCAB   50000
#define IMG     256
#define MROWS   (BATCH*NTOK) // 1284

typedef unsigned short u16;
typedef unsigned int u32;

// ---------------- scratch ----------------
__device__ float g_x  [MROWS*DIM];
__device__ float g_q  [MROWS*DIM];
__device__ float g_k  [MROWS*DIM];
__device__ float g_v  [MROWS*DIM];
__device__ float g_att[BATCH*HEADS*NTOK*NTOK];   // + patch-embed scratch
__device__ float g_h  [MROWS*MLPD];              // fp32 scratch (final proj out)
__device__ float g_temb_raw[BATCH*TDIM];
__device__ float g_t1 [BATCH*DIM];
__device__ float g_temb[BATCH*DIM];
__device__ float g_mod[BATCH*6*DIM];

// bf16 hi/lo activation buffers
__device__ __align__(16) u16 g_xn_h[MROWS*DIM];
__device__ __align__(16) u16 g_xn_l[MROWS*DIM];
__device__ __align__(16) u16 g_hh  [MROWS*MLPD];
__device__ __align__(16) u16 g_hl  [MROWS*MLPD];
__device__ __align__(16) u16 g_o_h [MROWS*DIM];
__device__ __align__(16) u16 g_o_l [MROWS*DIM];
__device__ __align__(16) u16 g_im_h[BATCH*NPATCH*PCH];
__device__ __align__(16) u16 g_im_l[BATCH*NPATCH*PCH];

// converted weights (hi/lo bf16)
#define OFF_PATCH 0
#define SZ_PATCH  (DIM*PCH)                  // 786432
#define OFF_WQ    (OFF_PATCH+SZ_PATCH)
#define SZ_QKVO   (NLAYERS*DIM*DIM)          // 2097152
#define OFF_WK    (OFF_WQ+SZ_QKVO)
#define OFF_WV    (OFF_WK+SZ_QKVO)
#define OFF_WO    (OFF_WV+SZ_QKVO)
#define OFF_WM1   (OFF_WO+SZ_QKVO)
#define SZ_WM     (NLAYERS*MLPD*DIM)         // 8388608
#define OFF_WM2   (OFF_WM1+SZ_WM)
#define OFF_FIN   (OFF_WM2+SZ_WM)
#define SZ_FIN    (PCH*DIM)
#define WTOTAL    (OFF_FIN+SZ_FIN)           // 26738688
__device__ __align__(16) u16 g_w_h[WTOTAL];
__device__ __align__(16) u16 g_w_l[WTOTAL];

// ---------------- helpers ----------------
__device__ __forceinline__ void split_store(float v, u16* h, u16* l, long idx) {
    __nv_bfloat16 hi = __float2bfloat16_rn(v);
    h[idx] = __bfloat16_as_ushort(hi);
    l[idx] = __bfloat16_as_ushort(__float2bfloat16_rn(v - __bfloat162float(hi)));
}

__global__ void cvt_hilo_kernel(const float* __restrict__ src, u16* __restrict__ h,
                                u16* __restrict__ l, int n) {
    int i = blockIdx.x * blockDim.x + threadIdx.x;
    if (i >= n) return;
    split_store(src[i], h, l, i);
}

// ---------------- embeddings ----------------
__global__ void embed_text_cls_kernel(const int* __restrict__ tokens,
                                      const float* __restrict__ W_tok,
                                      const float* __restrict__ pos_text,
                                      const float* __restrict__ cls_tok) {
    int idx = blockIdx.x * blockDim.x + threadIdx.x;
    if (idx >= BATCH * 65 * DIM) return;
    int d = idx % DIM;
    int t = (idx / DIM) % 65;
    int b = idx / (DIM * 65);
    float v;
    if (t < TEXT) {
        int tok = tokens[b * TEXT + t];
        v = W_tok[(long)d * VOCAB + tok] + pos_text[t * DIM + d];
    } else v = cls_tok[d];
    g_x[(b * NTOK + t) * DIM + d] = v;
}

__global__ void im2col_kernel(const float* __restrict__ img) {
    int idx = blockIdx.x * blockDim.x + threadIdx.x;
    if (idx >= BATCH * NPATCH * PCH) return;
    int c = idx % PCH;
    int p = (idx / PCH) % NPATCH;
    int b = idx / (PCH * NPATCH);
    int ch = c / 256;
    int pr = (c / 16) % 16;
    int pc = c % 16;
    int hp = p / 16, wp = p % 16;
    float v = img[((b * 3 + ch) * IMG + hp * 16 + pr) * IMG + wp * 16 + pc];
    split_store(v, g_im_h, g_im_l, idx);
}

__global__ void add_posimg_kernel(const float* __restrict__ pos_img) {
    int idx = blockIdx.x * blockDim.x + threadIdx.x;
    if (idx >= BATCH * NPATCH * DIM) return;
    int d = idx % DIM;
    int p = (idx / DIM) % NPATCH;
    int b = idx / (DIM * NPATCH);
    g_x[(b * NTOK + 65 + p) * DIM + d] = g_att[idx] + pos_img[p * DIM + d];
}

// ---------------- timestep embedding ----------------
__global__ void temb_raw_kernel(const int* __restrict__ tsteps) {
    int idx = blockIdx.x * blockDim.x + threadIdx.x;
    if (idx >= BATCH * TDIM) return;
    int i = idx % TDIM;
    int b = idx / TDIM;
    int j = i & 127;
    float f = expf(-logf(10000.0f) * (float)j / 128.0f);
    float a = (float)tsteps[b] * f;
    g_temb_raw[idx] = (i < 128) ? cosf(a) : sinf(a);
}

__global__ void t1_kernel(const float* __restrict__ W_t1, const float* __restrict__ b_t1) {
    int idx = blockIdx.x * blockDim.x + threadIdx.x;
    if (idx >= BATCH * DIM) return;
    int d = idx % DIM;
    int b = idx / DIM;
    float s = b_t1[d];
    const float* tr = g_temb_raw + b * TDIM;
    const float* w  = W_t1 + d * TDIM;
    for (int k = 0; k < TDIM; k++) s += tr[k] * w[k];
    g_t1[idx] = s / (1.0f + expf(-s));
}

__global__ void t2_kernel(const float* __restrict__ W_t2, const float* __restrict__ b_t2) {
    int idx = blockIdx.x * blockDim.x + threadIdx.x;
    if (idx >= BATCH * DIM) return;
    int d = idx % DIM;
    int b = idx / DIM;
    float s = b_t2[d];
    const float* h = g_t1 + b * DIM;
    const float* w = W_t2 + d * DIM;
    for (int k = 0; k < DIM; k++) s += h[k] * w[k];
    g_temb[idx] = s;
}

__global__ void silu_temb_kernel() {
    int idx = blockIdx.x * blockDim.x + threadIdx.x;
    if (idx >= BATCH * DIM) return;
    float v = g_temb[idx];
    g_t1[idx] = v / (1.0f + expf(-v));
}

// ---------------- scalar SGEMM (adaLN only: M=4) ----------------
__global__ void sgemm_kernel(const float* __restrict__ A, const float* __restrict__ W,
                             float* __restrict__ C, int M, int Nt, int K,
                             const float* __restrict__ bias) {
    __shared__ float As[16][64];
    __shared__ float Ws[16][64];
    int tid = threadIdx.x;
    int row0 = blockIdx.y * 64, col0 = blockIdx.x * 64;
    int tx = tid & 15, ty = tid >> 4;
    int lr = tid >> 2;
    int lk = (tid & 3) * 4;
    float acc[4][4];
#pragma unroll
    for (int i = 0; i < 4; i++)
#pragma unroll
        for (int j = 0; j < 4; j++) acc[i][j] = 0.0f;
    for (int k0 = 0; k0 < K; k0 += 16) {
        int arow = row0 + lr;
        if (arow < M) {
            const float* ap = A + (long)arow * K + k0 + lk;
#pragma unroll
            for (int i = 0; i < 4; i++) As[lk + i][lr] = ap[i];
        } else {
#pragma unroll
            for (int i = 0; i < 4; i++) As[lk + i][lr] = 0.0f;
        }
        const float* wp = W + (long)(col0 + lr) * K + k0 + lk;
#pragma unroll
        for (int i = 0; i < 4; i++) Ws[lk + i][lr] = wp[i];
        __syncthreads();
#pragma unroll
        for (int kk = 0; kk < 16; kk++) {
            float a[4], w[4];
#pragma unroll
            for (int i = 0; i < 4; i++) a[i] = As[kk][ty * 4 + i];
#pragma unroll
            for (int j = 0; j < 4; j++) w[j] = Ws[kk][tx * 4 + j];
#pragma unroll
            for (int i = 0; i < 4; i++)
#pragma unroll
                for (int j = 0; j < 4; j++) acc[i][j] += a[i] * w[j];
        }
        __syncthreads();
    }
#pragma unroll
    for (int i = 0; i < 4; i++) {
        int row = row0 + ty * 4 + i;
        if (row >= M) continue;
#pragma unroll
        for (int j = 0; j < 4; j++) {
            int col = col0 + tx * 4 + j;
            C[(long)row * Nt + col] = acc[i][j] + (bias ? bias[col] : 0.0f);
        }
    }
}

// ---------------- tensor-core GEMM (bf16 hi/lo inputs, ldmatrix + cp.async) ----------------
// smem layout per stage (bytes): A_hi@0 (64*80), A_lo@5120, W_hi@10240 (128*80), W_lo@20480
#define ST_A_LO 5120
#define ST_W_HI 10240
#define ST_W_LO 20480
#define STAGE   30720

__device__ __forceinline__ void cp16(u32 dst, const void* src, bool valid) {
    int sz = valid ? 16 : 0;
    asm volatile("cp.async.ca.shared.global [%0], [%1], 16, %2;\n" :: "r"(dst), "l"(src), "r"(sz));
}
__device__ __forceinline__ void cp_commit() { asm volatile("cp.async.commit_group;\n"); }
__device__ __forceinline__ void cp_wait0() { asm volatile("cp.async.wait_group 0;\n"); }
__device__ __forceinline__ void cp_wait1() { asm volatile("cp.async.wait_group 1;\n"); }

__device__ __forceinline__ void ldsm4(u32& r0, u32& r1, u32& r2, u32& r3, u32 addr) {
    asm volatile("ldmatrix.sync.aligned.m8n8.x4.shared.b16 {%0,%1,%2,%3}, [%4];\n"
                 : "=r"(r0), "=r"(r1), "=r"(r2), "=r"(r3) : "r"(addr));
}

__device__ __forceinline__ void mma16816(float* c, const u32* a, const u32* b) {
    asm volatile(
        "mma.sync.aligned.m16n8k16.row.col.f32.bf16.bf16.f32 "
        "{%0,%1,%2,%3}, {%4,%5,%6,%7}, {%8,%9}, {%0,%1,%2,%3};\n"
        : "+f"(c[0]), "+f"(c[1]), "+f"(c[2]), "+f"(c[3])
        : "r"(a[0]), "r"(a[1]), "r"(a[2]), "r"(a[3]), "r"(b[0]), "r"(b[1]));
}

__device__ __forceinline__ void gemm_stage_load(
    u32 sbase, int stage,
    const u16* __restrict__ Ah, const u16* __restrict__ Al,
    const u16* __restrict__ Wh, const u16* __restrict__ Wl,
    int row0, int col0, int k0, int M, int K, int tid)
{
    u32 sb = sbase + stage * STAGE;
#pragma unroll
    for (int i = 0; i < 2; i++) {
        int c = tid + i * 256;
        const u16* src = (c < 256) ? Ah : Al;
        u32 dofs = (c < 256) ? 0u : (u32)ST_A_LO;
        int idx = c & 255;
        int row = idx >> 2, q = idx & 3;
        const void* s = src + (long)(row0 + row) * K + k0 + q * 8;
        cp16(sb + dofs + row * 80 + q * 16, s, (row0 + row) < M);
    }
#pragma unroll
    for (int i = 0; i < 4; i++) {
        int c = tid + i * 256;
        const u16* src = (c < 512) ? Wh : Wl;
        u32 dofs = (c < 512) ? (u32)ST_W_HI : (u32)ST_W_LO;
        int idx = c & 511;
        int row = idx >> 2, q = idx & 3;
        const void* s = src + (long)(col0 + row) * K + k0 + q * 8;
        cp16(sb + dofs + row * 80 + q * 16, s, true);
    }
}

// epi: 0 = fp32 C (+bias); 1 = gelu -> bf16 hi/lo out; 2 = fp32 C += gate*acc
__global__ __launch_bounds__(256) void mma_gemm_kernel(
        const u16* __restrict__ Ah, const u16* __restrict__ Al,
        const u16* __restrict__ Wh, const u16* __restrict__ Wl,
        float* __restrict__ C, u16* __restrict__ Oh, u16* __restrict__ Ol,
        int M, int Nt, int K,
        const float* __restrict__ bias,
        const float* __restrict__ gate, int gate_ofs, int epi) {
    extern __shared__ char smem[];
    u32 sbase = (u32)__cvta_generic_to_shared(smem);

    int tid  = threadIdx.x;
    int lane = tid & 31;
    int warp = tid >> 5;
    int wm = warp >> 2;
    int wn = warp & 3;
    int row0 = blockIdx.y * 64;
    int col0 = blockIdx.x * 128;

    float acc[2][4][4];
#pragma unroll
    for (int i = 0; i < 2; i++)
#pragma unroll
        for (int j = 0; j < 4; j++)
#pragma unroll
            for (int t = 0; t < 4; t++) acc[i][j][t] = 0.0f;

    u32 a_lane_off = (lane & 15) * 80 + (lane >> 4) * 16;
    u32 w_lane_off = (((lane >> 4) & 1) * 8 + (lane & 7)) * 80 + ((lane >> 3) & 1) * 16;

    int KT = K >> 5;
    gemm_stage_load(sbase, 0, Ah, Al, Wh, Wl, row0, col0, 0, M, K, tid);
    cp_commit();

    for (int kt = 0; kt < KT; kt++) {
        if (kt + 1 < KT) {
            gemm_stage_load(sbase, (kt + 1) & 1, Ah, Al, Wh, Wl, row0, col0, (kt + 1) << 5, M, K, tid);
            cp_commit();
            cp_wait1();
        } else {
            cp_wait0();
        }
        __syncthreads();

        u32 sb = sbase + (kt & 1) * STAGE;
#pragma unroll
        for (int s = 0; s < 2; s++) {
            u32 ah[2][4], al[2][4];
#pragma unroll
            for (int mt = 0; mt < 2; mt++) {
                u32 aaddr = sb + (wm * 32 + mt * 16) * 80 + s * 32 + a_lane_off;
                ldsm4(ah[mt][0], ah[mt][1], ah[mt][2], ah[mt][3], aaddr);
                ldsm4(al[mt][0], al[mt][1], al[mt][2], al[mt][3], aaddr + ST_A_LO);
            }
            u32 bh[2][4], bl[2][4];
#pragma unroll
            for (int ntp = 0; ntp < 2; ntp++) {
                u32 waddr = sb + ST_W_HI + (wn * 32 + ntp * 16) * 80 + s * 32 + w_lane_off;
                ldsm4(bh[ntp][0], bh[ntp][1], bh[ntp][2], bh[ntp][3], waddr);
                ldsm4(bl[ntp][0], bl[ntp][1], bl[ntp][2], bl[ntp][3], waddr + (ST_W_LO - ST_W_HI));
            }
#pragma unroll
            for (int mt = 0; mt < 2; mt++)
#pragma unroll
                for (int nt = 0; nt < 4; nt++) {
                    const u32* Bh = &bh[nt >> 1][(nt & 1) * 2];
                    const u32* Bl = &bl[nt >> 1][(nt & 1) * 2];
                    mma16816(acc[mt][nt], ah[mt], Bh);
                    mma16816(acc[mt][nt], ah[mt], Bl);
                    mma16816(acc[mt][nt], al[mt], Bh);
                }
        }
        __syncthreads();
    }

    // epilogue
#pragma unroll
    for (int mt = 0; mt < 2; mt++)
#pragma unroll
        for (int nt = 0; nt < 4; nt++)
#pragma unroll
            for (int half = 0; half < 2; half++) {
                int row = row0 + wm * 32 + mt * 16 + (lane >> 2) + half * 8;
                if (row >= M) continue;
#pragma unroll
                for (int jj = 0; jj < 2; jj++) {
                    int col = col0 + wn * 32 + nt * 8 + (lane & 3) * 2 + jj;
                    float v = acc[mt][nt][half * 2 + jj];
                    long idx = (long)row * Nt + col;
                    if (epi == 0) {
                        if (bias) v += bias[col];
                        C[idx] = v;
                    } else if (epi == 1) {
                        float gu = 0.5f * v * (1.0f + erff(v * 0.70710678118654752f));
                        split_store(gu, Oh, Ol, idx);
                    } else {
                        int b = row / NTOK;
                        C[idx] += gate[b * 6 * DIM + gate_ofs + col] * v;
                    }
                }
            }
}

// ---------------- layernorm + adaLN modulation (writes bf16 hi/lo) ----------------
__global__ void ln_mod_kernel(const float* __restrict__ x,
                              u16* __restrict__ outh, u16* __restrict__ outl,
                              const float* __restrict__ g, const float* __restrict__ beta,
                              const float* __restrict__ mod, int sh_ofs, int sc_ofs) {
    int row = blockIdx.x;
    int b = row / NTOK;
    const float* xr = x + (long)row * DIM;
    __shared__ float red[256];
    int tid = threadIdx.x;
    float local[4];
    float s = 0.0f;
#pragma unroll
    for (int i = 0; i < 4; i++) { local[i] = xr[tid + i * 256]; s += local[i]; }
    red[tid] = s; __syncthreads();
    for (int o = 128; o > 0; o >>= 1) { if (tid < o) red[tid] += red[tid + o]; __syncthreads(); }
    float mean = red[0] * (1.0f / DIM);
    __syncthreads();
    float s2 = 0.0f;
#pragma unroll
    for (int i = 0; i < 4; i++) { float d = local[i] - mean; s2 += d * d; }
    red[tid] = s2; __syncthreads();
    for (int o = 128; o > 0; o >>= 1) { if (tid < o) red[tid] += red[tid + o]; __syncthreads(); }
    float inv = rsqrtf(red[0] * (1.0f / DIM) + 1e-5f);
#pragma unroll
    for (int i = 0; i < 4; i++) {
        int d = tid + i * 256;
        float v = (local[i] - mean) * inv * g[d] + beta[d];
        v = v * (1.0f + mod[b * 6 * DIM + sc_ofs + d]) + mod[b * 6 * DIM + sh_ofs + d];
        split_store(v, outh, outl, (long)row * DIM + d);
    }
}

__global__ void final_ln_kernel(const float* __restrict__ g, const float* __restrict__ beta) {
    int p = blockIdx.x % NPATCH;
    int b = blockIdx.x / NPATCH;
    const float* xr = g_x + (long)(b * NTOK + 65 + p) * DIM;
    __shared__ float red[256];
    int tid = threadIdx.x;
    float local[4];
    float s = 0.0f;
#pragma unroll
    for (int i = 0; i < 4; i++) { local[i] = xr[tid + i * 256]; s += local[i]; }
    red[tid] = s; __syncthreads();
    for (int o = 128; o > 0; o >>= 1) { if (tid < o) red[tid] += red[tid + o]; __syncthreads(); }
    float mean = red[0] * (1.0f / DIM);
    __syncthreads();
    float s2 = 0.0f;
#pragma unroll
    for (int i = 0; i < 4; i++) { float d = local[i] - mean; s2 += d * d; }
    red[tid] = s2; __syncthreads();
    for (int o = 128; o > 0; o >>= 1) { if (tid < o) red[tid] += red[tid + o]; __syncthreads(); }
    float inv = rsqrtf(red[0] * (1.0f / DIM) + 1e-5f);
#pragma unroll
    for (int i = 0; i < 4; i++) {
        int d = tid + i * 256;
        float v = (local[i] - mean) * inv * g[d] + beta[d];
        split_store(v, g_xn_h, g_xn_l, (long)blockIdx.x * DIM + d);
    }
}

// ---------------- RoPE ----------------
__global__ void rope_kernel() {
    int bi = blockIdx.x;
    float* buf = (bi >= MROWS * HEADS) ? g_k : g_q;
    int rh = bi % (MROWS * HEADS);
    int row = rh / HEADS, h = rh % HEADS;
    int n = row % NTOK;
    int i = threadIdx.x;
    __shared__ float sx[HD];
    float* p = buf + (long)row * DIM + h * HD;
    sx[i] = p[i];
    __syncthreads();
    float inv = powf(10000.0f, -(float)(2 * (i & 31)) / 64.0f);
    float ang = (float)n * inv;
    float cs = cosf(ang), sn = sinf(ang);
    float rot = (i < 32) ? -sx[2 * i + 1] : sx[2 * (i - 32)];
    p[i] = sx[i] * cs + rot * sn;
}

// ---------------- attention ----------------
__global__ void attn_scores_kernel() {
    int blk = blockIdx.x;
    int n = blk % NTOK;
    int bh = blk / NTOK;
    int h = bh % HEADS;
    int b = bh / HEADS;
    int tid = threadIdx.x;
    __shared__ float sq[HD];
    __shared__ float ss[NTOK];
    __shared__ float red[128];
    const float* qrow = g_q + (long)(b * NTOK + n) * DIM + h * HD;
    if (tid < HD) sq[tid] = qrow[tid];
    __syncthreads();
    float lmax = -1e30f;
    for (int m = tid; m < NTOK; m += 128) {
        const float* krow = g_k + (long)(b * NTOK + m) * DIM + h * HD;
        float s = 0.0f;
#pragma unroll 16
        for (int d = 0; d < HD; d++) s += sq[d] * krow[d];
        s *= 0.125f;
        ss[m] = s;
        lmax = fmaxf(lmax, s);
    }
    red[tid] = lmax; __syncthreads();
    for (int o = 64; o > 0; o >>= 1) { if (tid < o) red[tid] = fmaxf(red[tid], red[tid + o]); __syncthreads(); }
    float gmax = red[0]; __syncthreads();
    float lsum = 0.0f;
    for (int m = tid; m < NTOK; m += 128) {
        float e = __expf(ss[m] - gmax);
        ss[m] = e;
        lsum += e;
    }
    red[tid] = lsum; __syncthreads();
    for (int o = 64; o > 0; o >>= 1) { if (tid < o) red[tid] += red[tid + o]; __syncthreads(); }
    float invsum = 1.0f / red[0];
    float* arow = g_att + (long)blk * NTOK;
    for (int m = tid; m < NTOK; m += 128) arow[m] = ss[m] * invsum;
}

__global__ void attn_av_kernel() {
    int blk = blockIdx.x;
    int n = blk % NTOK;
    int bh = blk / NTOK;
    int h = bh % HEADS;
    int b = bh / HEADS;
    int tid = threadIdx.x;
    __shared__ float satt[NTOK];
    const float* arow = g_att + (long)blk * NTOK;
    for (int m = tid; m < NTOK; m += HD) satt[m] = arow[m];
    __syncthreads();
    const float* vbase = g_v + (long)b * NTOK * DIM + h * HD + tid;
    float acc = 0.0f;
    for (int m = 0; m < NTOK; m++) acc += satt[m] * vbase[(long)m * DIM];
    split_store(acc, g_o_h, g_o_l, (long)(b * NTOK + n) * DIM + h * HD + tid);
}

// ---------------- output unpatchify ----------------
__global__ void unpatch_kernel(float* __restrict__ out) {
    int idx = blockIdx.x * blockDim.x + threadIdx.x;
    if (idx >= BATCH * 3 * IMG * IMG) return;
    int c_img = idx % IMG;
    int r_img = (idx / IMG) % IMG;
    int ch = (idx / (IMG * IMG)) % 3;
    int b = idx / (3 * IMG * IMG);
    int hp = r_img / 16, pr = r_img % 16;
    int wp = c_img / 16, pc = c_img % 16;
    out[idx] = g_h[(long)(b * NPATCH + hp * 16 + wp) * PCH + ch * 256 + pr * 16 + pc];
}

// ---------------- host launch ----------------
static void* symaddr_raw(const void* sym) {
    void* p = nullptr;
    cudaGetSymbolAddress(&p, sym);
    return p;
}

extern "C" void kernel_launch(void* const* d_in, const int* in_sizes, int n_in,
                              void* d_out, int out_size) {
    const float* noisy    = (const float*)d_in[0];
    const int*   tokens   = (const int*)  d_in[1];
    const int*   tsteps   = (const int*)  d_in[2];
    const float* W_tok    = (const float*)d_in[3];
    const float* pos_text = (const float*)d_in[4];
    const float* W_patch  = (const float*)d_in[5];
    const float* pos_img  = (const float*)d_in[6];
    const float* cls_tok  = (const float*)d_in[7];
    const float* W_t1     = (const float*)d_in[8];
    const float* b_t1     = (const float*)d_in[9];
    const float* W_t2     = (const float*)d_in[10];
    const float* b_t2     = (const float*)d_in[11];
    const float* ln1_g    = (const float*)d_in[12];
    const float* ln1_b    = (const float*)d_in[13];
    const float* Wq       = (const float*)d_in[14];
    const float* Wk       = (const float*)d_in[15];
    const float* Wv       = (const float*)d_in[16];
    const float* Wo       = (const float*)d_in[17];
    const float* ln2_g    = (const float*)d_in[18];
    const float* ln2_b    = (const float*)d_in[19];
    const float* Wm1      = (const float*)d_in[20];
    const float* Wm2      = (const float*)d_in[21];
    const float* Wada     = (const float*)d_in[22];
    const float* b_ada    = (const float*)d_in[23];
    const float* fn_g     = (const float*)d_in[24];
    const float* fn_b     = (const float*)d_in[25];
    const float* W_final  = (const float*)d_in[26];
    const float* b_final  = (const float*)d_in[27];
    float* out = (float*)d_out;

    float* p_x    = (float*)symaddr_raw(g_x);
    float* p_att  = (float*)symaddr_raw(g_att);
    float* p_h    = (float*)symaddr_raw(g_h);
    float* p_t1   = (float*)symaddr_raw(g_t1);
    float* p_mod  = (float*)symaddr_raw(g_mod);
    u16* p_wh     = (u16*)symaddr_raw(g_w_h);
    u16* p_wl     = (u16*)symaddr_raw(g_w_l);
    u16* p_xnh    = (u16*)symaddr_raw(g_xn_h);
    u16* p_xnl    = (u16*)symaddr_raw(g_xn_l);
    u16* p_hh     = (u16*)symaddr_raw(g_hh);
    u16* p_hl     = (u16*)symaddr_raw(g_hl);
    u16* p_oh     = (u16*)symaddr_raw(g_o_h);
    u16* p_ol     = (u16*)symaddr_raw(g_o_l);
    u16* p_imh    = (u16*)symaddr_raw(g_im_h);
    u16* p_iml    = (u16*)symaddr_raw(g_im_l);
    float* p_q    = (float*)symaddr_raw(g_q);
    float* p_k    = (float*)symaddr_raw(g_k);
    float* p_v    = (float*)symaddr_raw(g_v);

    static bool smem_set = false;
    if (!smem_set) {
        cudaFuncSetAttribute(mma_gemm_kernel, cudaFuncAttributeMaxDynamicSharedMemorySize, 2 * STAGE);
        smem_set = true;
    }

    // ---- convert weights to bf16 hi/lo ----
    {
        auto cvt = [&](const float* src, long off, int n) {
            cvt_hilo_kernel<<<(n + 511) / 512, 512>>>(src, p_wh + off, p_wl + off, n);
        };
        cvt(W_patch, OFF_PATCH, SZ_PATCH);
        cvt(Wq, OFF_WQ, SZ_QKVO);
        cvt(Wk, OFF_WK, SZ_QKVO);
        cvt(Wv, OFF_WV, SZ_QKVO);
        cvt(Wo, OFF_WO, SZ_QKVO);
        cvt(Wm1, OFF_WM1, SZ_WM);
        cvt(Wm2, OFF_WM2, SZ_WM);
        cvt(W_final, OFF_FIN, SZ_FIN);
    }

    // ---- embeddings ----
    {
        int n1 = BATCH * 65 * DIM;
        embed_text_cls_kernel<<<(n1 + 255) / 256, 256>>>(tokens, W_tok, pos_text, cls_tok);
        int n2 = BATCH * NPATCH * PCH;
        im2col_kernel<<<(n2 + 255) / 256, 256>>>(noisy);
        mma_gemm_kernel<<<dim3(DIM / 128, (BATCH * NPATCH) / 64), 256, 2 * STAGE>>>(
            p_imh, p_iml, p_wh + OFF_PATCH, p_wl + OFF_PATCH,
            p_att, nullptr, nullptr, BATCH * NPATCH, DIM, PCH, nullptr, nullptr, 0, 0);
        int n3 = BATCH * NPATCH * DIM;
        add_posimg_kernel<<<(n3 + 255) / 256, 256>>>(pos_img);
    }

    // ---- timestep embedding ----
    temb_raw_kernel<<<(BATCH * TDIM + 255) / 256, 256>>>(tsteps);
    t1_kernel<<<(BATCH * DIM + 255) / 256, 256>>>(W_t1, b_t1);
    t2_kernel<<<(BATCH * DIM + 255) / 256, 256>>>(W_t2, b_t2);
    silu_temb_kernel<<<(BATCH * DIM + 255) / 256, 256>>>();

    int gy = (MROWS + 63) / 64;   // 21

    for (int l = 0; l < NLAYERS; l++) {
        long wq_o = OFF_WQ + (long)l * DIM * DIM;
        long wk_o = OFF_WK + (long)l * DIM * DIM;
        long wv_o = OFF_WV + (long)l * DIM * DIM;
        long wo_o = OFF_WO + (long)l * DIM * DIM;
        long wm1_o = OFF_WM1 + (long)l * MLPD * DIM;
        long wm2_o = OFF_WM2 + (long)l * DIM * MLPD;
        const float* Wada_l = Wada + (long)l * 6 * DIM * DIM;
        const float* bada_l = b_ada + (long)l * 6 * DIM;

        sgemm_kernel<<<dim3(6 * DIM / 64, 1), 256>>>(
            p_t1, Wada_l, p_mod, BATCH, 6 * DIM, DIM, bada_l);

        ln_mod_kernel<<<MROWS, 256>>>(p_x, p_xnh, p_xnl, ln1_g + l * DIM, ln1_b + l * DIM,
                                      p_mod, 0, DIM);

        mma_gemm_kernel<<<dim3(DIM / 128, gy), 256, 2 * STAGE>>>(
            p_xnh, p_xnl, p_wh + wq_o, p_wl + wq_o, p_q, nullptr, nullptr,
            MROWS, DIM, DIM, nullptr, nullptr, 0, 0);
        mma_gemm_kernel<<<dim3(DIM / 128, gy), 256, 2 * STAGE>>>(
            p_xnh, p_xnl, p_wh + wk_o, p_wl + wk_o, p_k, nullptr, nullptr,
            MROWS, DIM, DIM, nullptr, nullptr, 0, 0);
        mma_gemm_kernel<<<dim3(DIM / 128, gy), 256, 2 * STAGE>>>(
            p_xnh, p_xnl, p_wh + wv_o, p_wl + wv_o, p_v, nullptr, nullptr,
            MROWS, DIM, DIM, nullptr, nullptr, 0, 0);

        rope_kernel<<<2 * MROWS * HEADS, HD>>>();

        attn_scores_kernel<<<BATCH * HEADS * NTOK, 128>>>();
        attn_av_kernel<<<BATCH * HEADS * NTOK, HD>>>();

        mma_gemm_kernel<<<dim3(DIM / 128, gy), 256, 2 * STAGE>>>(
            p_oh, p_ol, p_wh + wo_o, p_wl + wo_o, p_x, nullptr, nullptr,
            MROWS, DIM, DIM, nullptr, p_mod, 2 * DIM, 2);

        ln_mod_kernel<<<MROWS, 256>>>(p_x, p_xnh, p_xnl, ln2_g + l * DIM, ln2_b + l * DIM,
                                      p_mod, 3 * DIM, 4 * DIM);

        mma_gemm_kernel<<<dim3(MLPD / 128, gy), 256, 2 * STAGE>>>(
            p_xnh, p_xnl, p_wh + wm1_o, p_wl + wm1_o, nullptr, p_hh, p_hl,
            MROWS, MLPD, DIM, nullptr, nullptr, 0, 1);
        mma_gemm_kernel<<<dim3(DIM / 128, gy), 256, 2 * STAGE>>>(
            p_hh, p_hl, p_wh + wm2_o, p_wl + wm2_o, p_x, nullptr, nullptr,
            MROWS, DIM, MLPD, nullptr, p_mod, 5 * DIM, 2);
    }

    // ---- final head ----
    final_ln_kernel<<<BATCH * NPATCH, 256>>>(fn_g, fn_b);
    mma_gemm_kernel<<<dim3(PCH / 128, (BATCH * NPATCH) / 64), 256, 2 * STAGE>>>(
        p_xnh, p_xnl, p_wh + OFF_FIN, p_wl + OFF_FIN, p_h, nullptr, nullptr,
        BATCH * NPATCH, PCH, DIM, b_final, nullptr, 0, 0);
    int n4 = BATCH * 3 * IMG * IMG;
    unpatch_kernel<<<(n4 + 255) / 256, 256>>>(out);
}

// round 4
// speedup vs baseline: 3.9843x; 2.5903x over previous
#include <cuda_runtime.h>
#include <cuda_bf16.h>
#include <math.h>

// ---------------- problem constants ----------------
#define BATCH   4
#define TEXT    64
#define NTOK    321
#define DIM     1024
#define HEADS   16
#define HD      64
#define MLPD    4096
#define NPATCH  256
#define PCH     768
#define TDIM    256
#define NLAYERS 2
#define VOCAB   50000
#define IMG     256
#define MROWS   (BATCH*NTOK) // 1284
#define DD      (DIM*DIM)

typedef unsigned short u16;
typedef unsigned int u32;

// ---------------- scratch ----------------
__device__ float g_x  [MROWS*DIM];
__device__ float g_qkv[MROWS*3*DIM];
__device__ float g_att[BATCH*NPATCH*DIM];        // patch-embed scratch
__device__ float g_h  [MROWS*MLPD];              // fp32 scratch (final proj out)
__device__ float g_temb_raw[BATCH*TDIM];
__device__ float g_t1 [BATCH*DIM];
__device__ float g_temb[BATCH*DIM];
__device__ float g_mod[BATCH*6*DIM];

// bf16 hi/lo activation buffers
__device__ __align__(16) u16 g_xn_h[MROWS*DIM];
__device__ __align__(16) u16 g_xn_l[MROWS*DIM];
__device__ __align__(16) u16 g_hh  [MROWS*MLPD];
__device__ __align__(16) u16 g_hl  [MROWS*MLPD];
__device__ __align__(16) u16 g_o_h [MROWS*DIM];
__device__ __align__(16) u16 g_o_l [MROWS*DIM];
__device__ __align__(16) u16 g_im_h[BATCH*NPATCH*PCH];
__device__ __align__(16) u16 g_im_l[BATCH*NPATCH*PCH];

// converted weights (hi/lo bf16); QKV interleaved per layer: [3*DIM rows][DIM]
#define OFF_PATCH 0
#define SZ_PATCH  (DIM*PCH)
#define OFF_QKV   (OFF_PATCH+SZ_PATCH)
#define SZ_QKV    (NLAYERS*3*DD)
#define OFF_WO    (OFF_QKV+SZ_QKV)
#define SZ_WO     (NLAYERS*DD)
#define OFF_WM1   (OFF_WO+SZ_WO)
#define SZ_WM     (NLAYERS*MLPD*DIM)
#define OFF_WM2   (OFF_WM1+SZ_WM)
#define OFF_FIN   (OFF_WM2+SZ_WM)
#define SZ_FIN    (PCH*DIM)
#define WTOTAL    (OFF_FIN+SZ_FIN)
__device__ __align__(16) u16 g_w_h[WTOTAL];
__device__ __align__(16) u16 g_w_l[WTOTAL];

// ---------------- helpers ----------------
__device__ __forceinline__ void split_store(float v, u16* h, u16* l, long idx) {
    __nv_bfloat16 hi = __float2bfloat16_rn(v);
    h[idx] = __bfloat16_as_ushort(hi);
    l[idx] = __bfloat16_as_ushort(__float2bfloat16_rn(v - __bfloat162float(hi)));
}

__device__ __forceinline__ u16 bf_hi(float v) {
    return __bfloat16_as_ushort(__float2bfloat16_rn(v));
}

// ---------------- mega weight conversion (one launch, float4) ----------------
__global__ void cvt_all_kernel(const float* __restrict__ Wp,
                               const float* __restrict__ Wq, const float* __restrict__ Wk,
                               const float* __restrict__ Wv, const float* __restrict__ Wo,
                               const float* __restrict__ Wm1, const float* __restrict__ Wm2,
                               const float* __restrict__ Wf) {
    long q = (long)blockIdx.x * blockDim.x + threadIdx.x;
    long nq = WTOTAL / 4;
    if (q >= nq) return;
    long idx = q * 4;
    const float* src;
    long sofs;
    if (idx < OFF_QKV) { src = Wp; sofs = idx; }
    else if (idx < OFF_WO) {
        long rel = idx - OFF_QKV;
        long l = rel / (3 * (long)DD);
        long r2 = rel % (3 * (long)DD);
        long which = r2 / DD;
        long inner = r2 % DD;
        src = (which == 0) ? Wq : (which == 1) ? Wk : Wv;
        sofs = l * DD + inner;
    } else if (idx < OFF_WM1) { src = Wo; sofs = idx - OFF_WO; }
    else if (idx < OFF_WM2) { src = Wm1; sofs = idx - OFF_WM1; }
    else if (idx < OFF_FIN) { src = Wm2; sofs = idx - OFF_WM2; }
    else { src = Wf; sofs = idx - OFF_FIN; }
    float4 v = *(const float4*)(src + sofs);
    ushort4 h, l4;
    h.x = bf_hi(v.x); h.y = bf_hi(v.y); h.z = bf_hi(v.z); h.w = bf_hi(v.w);
    l4.x = bf_hi(v.x - __bfloat162float(__ushort_as_bfloat16(h.x)));
    l4.y = bf_hi(v.y - __bfloat162float(__ushort_as_bfloat16(h.y)));
    l4.z = bf_hi(v.z - __bfloat162float(__ushort_as_bfloat16(h.z)));
    l4.w = bf_hi(v.w - __bfloat162float(__ushort_as_bfloat16(h.w)));
    *(ushort4*)(g_w_h + idx) = h;
    *(ushort4*)(g_w_l + idx) = l4;
}

// ---------------- embeddings ----------------
__global__ void embed_text_cls_kernel(const int* __restrict__ tokens,
                                      const float* __restrict__ W_tok,
                                      const float* __restrict__ pos_text,
                                      const float* __restrict__ cls_tok) {
    int idx = blockIdx.x * blockDim.x + threadIdx.x;
    if (idx >= BATCH * 65 * DIM) return;
    int d = idx % DIM;
    int t = (idx / DIM) % 65;
    int b = idx / (DIM * 65);
    float v;
    if (t < TEXT) {
        int tok = tokens[b * TEXT + t];
        v = W_tok[(long)d * VOCAB + tok] + pos_text[t * DIM + d];
    } else v = cls_tok[d];
    g_x[(b * NTOK + t) * DIM + d] = v;
}

__global__ void im2col_kernel(const float* __restrict__ img) {
    int idx = blockIdx.x * blockDim.x + threadIdx.x;
    if (idx >= BATCH * NPATCH * PCH) return;
    int c = idx % PCH;
    int p = (idx / PCH) % NPATCH;
    int b = idx / (PCH * NPATCH);
    int ch = c / 256;
    int pr = (c / 16) % 16;
    int pc = c % 16;
    int hp = p / 16, wp = p % 16;
    float v = img[((b * 3 + ch) * IMG + hp * 16 + pr) * IMG + wp * 16 + pc];
    split_store(v, g_im_h, g_im_l, idx);
}

__global__ void add_posimg_kernel(const float* __restrict__ pos_img) {
    int idx = blockIdx.x * blockDim.x + threadIdx.x;
    if (idx >= BATCH * NPATCH * DIM) return;
    int d = idx % DIM;
    int p = (idx / DIM) % NPATCH;
    int b = idx / (DIM * NPATCH);
    g_x[(b * NTOK + 65 + p) * DIM + d] = g_att[idx] + pos_img[p * DIM + d];
}

// ---------------- timestep embedding ----------------
__global__ void temb_raw_kernel(const int* __restrict__ tsteps) {
    int idx = blockIdx.x * blockDim.x + threadIdx.x;
    if (idx >= BATCH * TDIM) return;
    int i = idx % TDIM;
    int b = idx / TDIM;
    int j = i & 127;
    float f = expf(-logf(10000.0f) * (float)j / 128.0f);
    float a = (float)tsteps[b] * f;
    g_temb_raw[idx] = (i < 128) ? cosf(a) : sinf(a);
}

__global__ void t1_kernel(const float* __restrict__ W_t1, const float* __restrict__ b_t1) {
    int idx = blockIdx.x * blockDim.x + threadIdx.x;
    if (idx >= BATCH * DIM) return;
    int d = idx % DIM;
    int b = idx / DIM;
    float s = b_t1[d];
    const float* tr = g_temb_raw + b * TDIM;
    const float* w  = W_t1 + d * TDIM;
    for (int k = 0; k < TDIM; k++) s += tr[k] * w[k];
    g_t1[idx] = s / (1.0f + expf(-s));
}

__global__ void t2_kernel(const float* __restrict__ W_t2, const float* __restrict__ b_t2) {
    int idx = blockIdx.x * blockDim.x + threadIdx.x;
    if (idx >= BATCH * DIM) return;
    int d = idx % DIM;
    int b = idx / DIM;
    float s = b_t2[d];
    const float* h = g_t1 + b * DIM;
    const float* w = W_t2 + d * DIM;
    for (int k = 0; k < DIM; k++) s += h[k] * w[k];
    g_temb[idx] = s;
}

__global__ void silu_temb_kernel() {
    int idx = blockIdx.x * blockDim.x + threadIdx.x;
    if (idx >= BATCH * DIM) return;
    float v = g_temb[idx];
    g_t1[idx] = v / (1.0f + expf(-v));
}

// ---------------- scalar SGEMM (adaLN only: M=4) ----------------
__global__ void sgemm_kernel(const float* __restrict__ A, const float* __restrict__ W,
                             float* __restrict__ C, int M, int Nt, int K,
                             const float* __restrict__ bias) {
    __shared__ float As[16][64];
    __shared__ float Ws[16][64];
    int tid = threadIdx.x;
    int row0 = blockIdx.y * 64, col0 = blockIdx.x * 64;
    int tx = tid & 15, ty = tid >> 4;
    int lr = tid >> 2;
    int lk = (tid & 3) * 4;
    float acc[4][4];
#pragma unroll
    for (int i = 0; i < 4; i++)
#pragma unroll
        for (int j = 0; j < 4; j++) acc[i][j] = 0.0f;
    for (int k0 = 0; k0 < K; k0 += 16) {
        int arow = row0 + lr;
        if (arow < M) {
            const float* ap = A + (long)arow * K + k0 + lk;
#pragma unroll
            for (int i = 0; i < 4; i++) As[lk + i][lr] = ap[i];
        } else {
#pragma unroll
            for (int i = 0; i < 4; i++) As[lk + i][lr] = 0.0f;
        }
        const float* wp = W + (long)(col0 + lr) * K + k0 + lk;
#pragma unroll
        for (int i = 0; i < 4; i++) Ws[lk + i][lr] = wp[i];
        __syncthreads();
#pragma unroll
        for (int kk = 0; kk < 16; kk++) {
            float a[4], w[4];
#pragma unroll
            for (int i = 0; i < 4; i++) a[i] = As[kk][ty * 4 + i];
#pragma unroll
            for (int j = 0; j < 4; j++) w[j] = Ws[kk][tx * 4 + j];
#pragma unroll
            for (int i = 0; i < 4; i++)
#pragma unroll
                for (int j = 0; j < 4; j++) acc[i][j] += a[i] * w[j];
        }
        __syncthreads();
    }
#pragma unroll
    for (int i = 0; i < 4; i++) {
        int row = row0 + ty * 4 + i;
        if (row >= M) continue;
#pragma unroll
        for (int j = 0; j < 4; j++) {
            int col = col0 + tx * 4 + j;
            C[(long)row * Nt + col] = acc[i][j] + (bias ? bias[col] : 0.0f);
        }
    }
}

// ---------------- tensor-core GEMM (bf16 hi/lo inputs, ldmatrix + cp.async) ----------------
#define ST_A_LO 5120
#define ST_W_HI 10240
#define ST_W_LO 20480
#define STAGE   30720

__device__ __forceinline__ void cp16(u32 dst, const void* src, bool valid) {
    int sz = valid ? 16 : 0;
    asm volatile("cp.async.ca.shared.global [%0], [%1], 16, %2;\n" :: "r"(dst), "l"(src), "r"(sz));
}
__device__ __forceinline__ void cp_commit() { asm volatile("cp.async.commit_group;\n"); }
__device__ __forceinline__ void cp_wait0() { asm volatile("cp.async.wait_group 0;\n"); }
__device__ __forceinline__ void cp_wait1() { asm volatile("cp.async.wait_group 1;\n"); }

__device__ __forceinline__ void ldsm4(u32& r0, u32& r1, u32& r2, u32& r3, u32 addr) {
    asm volatile("ldmatrix.sync.aligned.m8n8.x4.shared.b16 {%0,%1,%2,%3}, [%4];\n"
                 : "=r"(r0), "=r"(r1), "=r"(r2), "=r"(r3) : "r"(addr));
}

__device__ __forceinline__ void mma16816(float* c, const u32* a, const u32* b) {
    asm volatile(
        "mma.sync.aligned.m16n8k16.row.col.f32.bf16.bf16.f32 "
        "{%0,%1,%2,%3}, {%4,%5,%6,%7}, {%8,%9}, {%0,%1,%2,%3};\n"
        : "+f"(c[0]), "+f"(c[1]), "+f"(c[2]), "+f"(c[3])
        : "r"(a[0]), "r"(a[1]), "r"(a[2]), "r"(a[3]), "r"(b[0]), "r"(b[1]));
}

__device__ __forceinline__ void gemm_stage_load(
    u32 sbase, int stage,
    const u16* __restrict__ Ah, const u16* __restrict__ Al,
    const u16* __restrict__ Wh, const u16* __restrict__ Wl,
    int row0, int col0, int k0, int M, int K, int tid)
{
    u32 sb = sbase + stage * STAGE;
#pragma unroll
    for (int i = 0; i < 2; i++) {
        int c = tid + i * 256;
        const u16* src = (c < 256) ? Ah : Al;
        u32 dofs = (c < 256) ? 0u : (u32)ST_A_LO;
        int idx = c & 255;
        int row = idx >> 2, q = idx & 3;
        const void* s = src + (long)(row0 + row) * K + k0 + q * 8;
        cp16(sb + dofs + row * 80 + q * 16, s, (row0 + row) < M);
    }
#pragma unroll
    for (int i = 0; i < 4; i++) {
        int c = tid + i * 256;
        const u16* src = (c < 512) ? Wh : Wl;
        u32 dofs = (c < 512) ? (u32)ST_W_HI : (u32)ST_W_LO;
        int idx = c & 511;
        int row = idx >> 2, q = idx & 3;
        const void* s = src + (long)(col0 + row) * K + k0 + q * 8;
        cp16(sb + dofs + row * 80 + q * 16, s, true);
    }
}

// epi: 0 = fp32 C (+bias); 1 = gelu -> bf16 hi/lo out; 2 = fp32 C += gate*acc
__global__ __launch_bounds__(256) void mma_gemm_kernel(
        const u16* __restrict__ Ah, const u16* __restrict__ Al,
        const u16* __restrict__ Wh, const u16* __restrict__ Wl,
        float* __restrict__ C, u16* __restrict__ Oh, u16* __restrict__ Ol,
        int M, int Nt, int K,
        const float* __restrict__ bias,
        const float* __restrict__ gate, int gate_ofs, int epi) {
    extern __shared__ char smem[];
    u32 sbase = (u32)__cvta_generic_to_shared(smem);

    int tid  = threadIdx.x;
    int lane = tid & 31;
    int warp = tid >> 5;
    int wm = warp >> 2;
    int wn = warp & 3;
    int row0 = blockIdx.y * 64;
    int col0 = blockIdx.x * 128;

    float acc[2][4][4];
#pragma unroll
    for (int i = 0; i < 2; i++)
#pragma unroll
        for (int j = 0; j < 4; j++)
#pragma unroll
            for (int t = 0; t < 4; t++) acc[i][j][t] = 0.0f;

    u32 a_lane_off = (lane & 15) * 80 + (lane >> 4) * 16;
    u32 w_lane_off = (((lane >> 4) & 1) * 8 + (lane & 7)) * 80 + ((lane >> 3) & 1) * 16;

    int KT = K >> 5;
    gemm_stage_load(sbase, 0, Ah, Al, Wh, Wl, row0, col0, 0, M, K, tid);
    cp_commit();

    for (int kt = 0; kt < KT; kt++) {
        if (kt + 1 < KT) {
            gemm_stage_load(sbase, (kt + 1) & 1, Ah, Al, Wh, Wl, row0, col0, (kt + 1) << 5, M, K, tid);
            cp_commit();
            cp_wait1();
        } else {
            cp_wait0();
        }
        __syncthreads();

        u32 sb = sbase + (kt & 1) * STAGE;
#pragma unroll
        for (int s = 0; s < 2; s++) {
            u32 ah[2][4], al[2][4];
#pragma unroll
            for (int mt = 0; mt < 2; mt++) {
                u32 aaddr = sb + (wm * 32 + mt * 16) * 80 + s * 32 + a_lane_off;
                ldsm4(ah[mt][0], ah[mt][1], ah[mt][2], ah[mt][3], aaddr);
                ldsm4(al[mt][0], al[mt][1], al[mt][2], al[mt][3], aaddr + ST_A_LO);
            }
            u32 bh[2][4], bl[2][4];
#pragma unroll
            for (int ntp = 0; ntp < 2; ntp++) {
                u32 waddr = sb + ST_W_HI + (wn * 32 + ntp * 16) * 80 + s * 32 + w_lane_off;
                ldsm4(bh[ntp][0], bh[ntp][1], bh[ntp][2], bh[ntp][3], waddr);
                ldsm4(bl[ntp][0], bl[ntp][1], bl[ntp][2], bl[ntp][3], waddr + (ST_W_LO - ST_W_HI));
            }
#pragma unroll
            for (int mt = 0; mt < 2; mt++)
#pragma unroll
                for (int nt = 0; nt < 4; nt++) {
                    const u32* Bh = &bh[nt >> 1][(nt & 1) * 2];
                    const u32* Bl = &bl[nt >> 1][(nt & 1) * 2];
                    mma16816(acc[mt][nt], ah[mt], Bh);
                    mma16816(acc[mt][nt], ah[mt], Bl);
                    mma16816(acc[mt][nt], al[mt], Bh);
                }
        }
        __syncthreads();
    }

#pragma unroll
    for (int mt = 0; mt < 2; mt++)
#pragma unroll
        for (int nt = 0; nt < 4; nt++)
#pragma unroll
            for (int half = 0; half < 2; half++) {
                int row = row0 + wm * 32 + mt * 16 + (lane >> 2) + half * 8;
                if (row >= M) continue;
#pragma unroll
                for (int jj = 0; jj < 2; jj++) {
                    int col = col0 + wn * 32 + nt * 8 + (lane & 3) * 2 + jj;
                    float v = acc[mt][nt][half * 2 + jj];
                    long idx = (long)row * Nt + col;
                    if (epi == 0) {
                        if (bias) v += bias[col];
                        C[idx] = v;
                    } else if (epi == 1) {
                        float gu = 0.5f * v * (1.0f + erff(v * 0.70710678118654752f));
                        split_store(gu, Oh, Ol, idx);
                    } else {
                        int b = row / NTOK;
                        C[idx] += gate[b * 6 * DIM + gate_ofs + col] * v;
                    }
                }
            }
}

// ---------------- layernorm + adaLN modulation (writes bf16 hi/lo) ----------------
__global__ void ln_mod_kernel(const float* __restrict__ x,
                              u16* __restrict__ outh, u16* __restrict__ outl,
                              const float* __restrict__ g, const float* __restrict__ beta,
                              const float* __restrict__ mod, int sh_ofs, int sc_ofs) {
    int row = blockIdx.x;
    int b = row / NTOK;
    const float* xr = x + (long)row * DIM;
    __shared__ float red[256];
    int tid = threadIdx.x;
    float local[4];
    float s = 0.0f;
#pragma unroll
    for (int i = 0; i < 4; i++) { local[i] = xr[tid + i * 256]; s += local[i]; }
    red[tid] = s; __syncthreads();
    for (int o = 128; o > 0; o >>= 1) { if (tid < o) red[tid] += red[tid + o]; __syncthreads(); }
    float mean = red[0] * (1.0f / DIM);
    __syncthreads();
    float s2 = 0.0f;
#pragma unroll
    for (int i = 0; i < 4; i++) { float d = local[i] - mean; s2 += d * d; }
    red[tid] = s2; __syncthreads();
    for (int o = 128; o > 0; o >>= 1) { if (tid < o) red[tid] += red[tid + o]; __syncthreads(); }
    float inv = rsqrtf(red[0] * (1.0f / DIM) + 1e-5f);
#pragma unroll
    for (int i = 0; i < 4; i++) {
        int d = tid + i * 256;
        float v = (local[i] - mean) * inv * g[d] + beta[d];
        v = v * (1.0f + mod[b * 6 * DIM + sc_ofs + d]) + mod[b * 6 * DIM + sh_ofs + d];
        split_store(v, outh, outl, (long)row * DIM + d);
    }
}

__global__ void final_ln_kernel(const float* __restrict__ g, const float* __restrict__ beta) {
    int p = blockIdx.x % NPATCH;
    int b = blockIdx.x / NPATCH;
    const float* xr = g_x + (long)(b * NTOK + 65 + p) * DIM;
    __shared__ float red[256];
    int tid = threadIdx.x;
    float local[4];
    float s = 0.0f;
#pragma unroll
    for (int i = 0; i < 4; i++) { local[i] = xr[tid + i * 256]; s += local[i]; }
    red[tid] = s; __syncthreads();
    for (int o = 128; o > 0; o >>= 1) { if (tid < o) red[tid] += red[tid + o]; __syncthreads(); }
    float mean = red[0] * (1.0f / DIM);
    __syncthreads();
    float s2 = 0.0f;
#pragma unroll
    for (int i = 0; i < 4; i++) { float d = local[i] - mean; s2 += d * d; }
    red[tid] = s2; __syncthreads();
    for (int o = 128; o > 0; o >>= 1) { if (tid < o) red[tid] += red[tid + o]; __syncthreads(); }
    float inv = rsqrtf(red[0] * (1.0f / DIM) + 1e-5f);
#pragma unroll
    for (int i = 0; i < 4; i++) {
        int d = tid + i * 256;
        float v = (local[i] - mean) * inv * g[d] + beta[d];
        split_store(v, g_xn_h, g_xn_l, (long)blockIdx.x * DIM + d);
    }
}

// ---------------- fused flash attention (RoPE + QK^T + softmax + AV) ----------------
// grid (6, 64): x = q-tile (64 rows), y = b*HEADS+h. 256 threads.
// smem floats: sq[64][68] | skv[32][68] | S[64][352]
#define FA_SQ  0
#define FA_KV  (64*68)
#define FA_S   (FA_KV + 32*68)
#define FA_TOT (FA_S + 64*352)            // 29056 floats = 116224 B
#define ROPE_C 0.28782313662425574f      // ln(10000)/32

__global__ __launch_bounds__(256) void flash_attn_kernel(
        const float* __restrict__ qkv, u16* __restrict__ oh, u16* __restrict__ ol) {
    extern __shared__ float sm[];
    int tile = blockIdx.x;
    int bh = blockIdx.y;
    int h = bh % HEADS, b = bh / HEADS;
    int tid = threadIdx.x, lane = tid & 31, warp = tid >> 5;

    // ---- load Q tile ----
    for (int i = tid; i < 64 * 64; i += 256) {
        int r = i >> 6, d = i & 63;
        int grow = tile * 64 + r;
        float v = 0.f;
        if (grow < NTOK) v = qkv[(long)(b * NTOK + grow) * 3072 + h * HD + d];
        sm[FA_SQ + r * 68 + d] = v;
    }
    __syncthreads();
    // ---- RoPE on Q (register-staged) ----
    {
        float tmp[16];
#pragma unroll
        for (int t = 0; t < 16; t++) {
            int i = tid + t * 256;
            int r = i >> 6, d = i & 63;
            int grow = tile * 64 + r;
            float x = sm[FA_SQ + r * 68 + d];
            float pr = (d < 32) ? -sm[FA_SQ + r * 68 + 2 * d + 1] : sm[FA_SQ + r * 68 + 2 * (d - 32)];
            float fr = __expf(-(float)(d & 31) * ROPE_C);
            float c, s;
            sincosf((float)grow * fr, &c, &s);
            tmp[t] = x * c + pr * s;
        }
        __syncthreads();
#pragma unroll
        for (int t = 0; t < 16; t++) {
            int i = tid + t * 256;
            sm[FA_SQ + (i >> 6) * 68 + (i & 63)] = tmp[t];
        }
    }

    // ---- pass 1: scores ----
    for (int c = 0; c < 11; c++) {
        __syncthreads();
        for (int i = tid; i < 32 * 64; i += 256) {
            int j = i >> 6, d = i & 63;
            int krow = c * 32 + j;
            float v = 0.f;
            if (krow < NTOK) v = qkv[(long)(b * NTOK + krow) * 3072 + DIM + h * HD + d];
            sm[FA_KV + j * 68 + d] = v;
        }
        __syncthreads();
        {
            float tmp[8];
#pragma unroll
            for (int t = 0; t < 8; t++) {
                int i = tid + t * 256;
                int j = i >> 6, d = i & 63;
                float x = sm[FA_KV + j * 68 + d];
                float pr = (d < 32) ? -sm[FA_KV + j * 68 + 2 * d + 1] : sm[FA_KV + j * 68 + 2 * (d - 32)];
                float fr = __expf(-(float)(d & 31) * ROPE_C);
                float cc, ss;
                sincosf((float)(c * 32 + j) * fr, &cc, &ss);
                tmp[t] = x * cc + pr * ss;
            }
            __syncthreads();
#pragma unroll
            for (int t = 0; t < 8; t++) {
                int i = tid + t * 256;
                sm[FA_KV + (i >> 6) * 68 + (i & 63)] = tmp[t];
            }
        }
        __syncthreads();
        // scores: warp handles rows warp*8..+7; lane handles k column c*32+lane
        bool kvalid = (c * 32 + lane) < NTOK;
        const float* kr = &sm[FA_KV + lane * 68];
        float sacc[8];
#pragma unroll
        for (int r8 = 0; r8 < 8; r8++) sacc[r8] = 0.f;
#pragma unroll
        for (int dq = 0; dq < 16; dq++) {
            float4 kv = *(const float4*)(kr + dq * 4);
#pragma unroll
            for (int r8 = 0; r8 < 8; r8++) {
                float4 qv = *(const float4*)&sm[FA_SQ + (warp * 8 + r8) * 68 + dq * 4];
                sacc[r8] += qv.x * kv.x + qv.y * kv.y + qv.z * kv.z + qv.w * kv.w;
            }
        }
#pragma unroll
        for (int r8 = 0; r8 < 8; r8++) {
            int r = warp * 8 + r8;
            sm[FA_S + r * 352 + c * 32 + lane] = kvalid ? sacc[r8] * 0.125f : -1e30f;
        }
    }

    // ---- softmax (rows are warp-private) ----
    float invr[8];
#pragma unroll
    for (int r8 = 0; r8 < 8; r8++) {
        float* Sr = &sm[FA_S + (warp * 8 + r8) * 352];
        float mx = -1e30f;
#pragma unroll
        for (int k = 0; k < 11; k++) mx = fmaxf(mx, Sr[lane + k * 32]);
#pragma unroll
        for (int o = 16; o > 0; o >>= 1) mx = fmaxf(mx, __shfl_xor_sync(0xffffffffu, mx, o));
        float sum = 0.f;
#pragma unroll
        for (int k = 0; k < 11; k++) {
            float e = __expf(Sr[lane + k * 32] - mx);
            Sr[lane + k * 32] = e;
            sum += e;
        }
#pragma unroll
        for (int o = 16; o > 0; o >>= 1) sum += __shfl_xor_sync(0xffffffffu, sum, o);
        invr[r8] = 1.0f / sum;
    }

    // ---- pass 2: AV ----
    float acc0[8], acc1[8];
#pragma unroll
    for (int r8 = 0; r8 < 8; r8++) { acc0[r8] = 0.f; acc1[r8] = 0.f; }
    for (int c = 0; c < 11; c++) {
        __syncthreads();
        for (int i = tid; i < 32 * 64; i += 256) {
            int j = i >> 6, d = i & 63;
            int vrow = c * 32 + j;
            float v = 0.f;
            if (vrow < NTOK) v = qkv[(long)(b * NTOK + vrow) * 3072 + 2 * DIM + h * HD + d];
            sm[FA_KV + j * 68 + d] = v;
        }
        __syncthreads();
#pragma unroll
        for (int jq = 0; jq < 8; jq++) {
            float v0[4], v1[4];
#pragma unroll
            for (int t = 0; t < 4; t++) {
                v0[t] = sm[FA_KV + (jq * 4 + t) * 68 + lane];
                v1[t] = sm[FA_KV + (jq * 4 + t) * 68 + lane + 32];
            }
#pragma unroll
            for (int r8 = 0; r8 < 8; r8++) {
                float4 p = *(const float4*)&sm[FA_S + (warp * 8 + r8) * 352 + c * 32 + jq * 4];
                acc0[r8] += p.x * v0[0] + p.y * v0[1] + p.z * v0[2] + p.w * v0[3];
                acc1[r8] += p.x * v1[0] + p.y * v1[1] + p.z * v1[2] + p.w * v1[3];
            }
        }
    }

    // ---- epilogue ----
#pragma unroll
    for (int r8 = 0; r8 < 8; r8++) {
        int grow = tile * 64 + warp * 8 + r8;
        if (grow >= NTOK) continue;
        long o = (long)(b * NTOK + grow) * DIM + h * HD + lane;
        split_store(acc0[r8] * invr[r8], oh, ol, o);
        split_store(acc1[r8] * invr[r8], oh, ol, o + 32);
    }
}

// ---------------- output unpatchify ----------------
__global__ void unpatch_kernel(float* __restrict__ out) {
    int idx = blockIdx.x * blockDim.x + threadIdx.x;
    if (idx >= BATCH * 3 * IMG * IMG) return;
    int c_img = idx % IMG;
    int r_img = (idx / IMG) % IMG;
    int ch = (idx / (IMG * IMG)) % 3;
    int b = idx / (3 * IMG * IMG);
    int hp = r_img / 16, pr = r_img % 16;
    int wp = c_img / 16, pc = c_img % 16;
    out[idx] = g_h[(long)(b * NPATCH + hp * 16 + wp) * PCH + ch * 256 + pr * 16 + pc];
}

// ---------------- host launch ----------------
static void* symaddr_raw(const void* sym) {
    void* p = nullptr;
    cudaGetSymbolAddress(&p, sym);
    return p;
}

extern "C" void kernel_launch(void* const* d_in, const int* in_sizes, int n_in,
                              void* d_out, int out_size) {
    const float* noisy    = (const float*)d_in[0];
    const int*   tokens   = (const int*)  d_in[1];
    const int*   tsteps   = (const int*)  d_in[2];
    const float* W_tok    = (const float*)d_in[3];
    const float* pos_text = (const float*)d_in[4];
    const float* W_patch  = (const float*)d_in[5];
    const float* pos_img  = (const float*)d_in[6];
    const float* cls_tok  = (const float*)d_in[7];
    const float* W_t1     = (const float*)d_in[8];
    const float* b_t1     = (const float*)d_in[9];
    const float* W_t2     = (const float*)d_in[10];
    const float* b_t2     = (const float*)d_in[11];
    const float* ln1_g    = (const float*)d_in[12];
    const float* ln1_b    = (const float*)d_in[13];
    const float* Wq       = (const float*)d_in[14];
    const float* Wk       = (const float*)d_in[15];
    const float* Wv       = (const float*)d_in[16];
    const float* Wo       = (const float*)d_in[17];
    const float* ln2_g    = (const float*)d_in[18];
    const float* ln2_b    = (const float*)d_in[19];
    const float* Wm1      = (const float*)d_in[20];
    const float* Wm2      = (const float*)d_in[21];
    const float* Wada     = (const float*)d_in[22];
    const float* b_ada    = (const float*)d_in[23];
    const float* fn_g     = (const float*)d_in[24];
    const float* fn_b     = (const float*)d_in[25];
    const float* W_final  = (const float*)d_in[26];
    const float* b_final  = (const float*)d_in[27];
    float* out = (float*)d_out;

    float* p_x    = (float*)symaddr_raw(g_x);
    float* p_qkv  = (float*)symaddr_raw(g_qkv);
    float* p_att  = (float*)symaddr_raw(g_att);
    float* p_h    = (float*)symaddr_raw(g_h);
    float* p_t1   = (float*)symaddr_raw(g_t1);
    float* p_mod  = (float*)symaddr_raw(g_mod);
    u16* p_wh     = (u16*)symaddr_raw(g_w_h);
    u16* p_wl     = (u16*)symaddr_raw(g_w_l);
    u16* p_xnh    = (u16*)symaddr_raw(g_xn_h);
    u16* p_xnl    = (u16*)symaddr_raw(g_xn_l);
    u16* p_hh     = (u16*)symaddr_raw(g_hh);
    u16* p_hl     = (u16*)symaddr_raw(g_hl);
    u16* p_oh     = (u16*)symaddr_raw(g_o_h);
    u16* p_ol     = (u16*)symaddr_raw(g_o_l);
    u16* p_imh    = (u16*)symaddr_raw(g_im_h);
    u16* p_iml    = (u16*)symaddr_raw(g_im_l);

    static bool attr_set = false;
    if (!attr_set) {
        cudaFuncSetAttribute(mma_gemm_kernel, cudaFuncAttributeMaxDynamicSharedMemorySize, 2 * STAGE);
        cudaFuncSetAttribute(flash_attn_kernel, cudaFuncAttributeMaxDynamicSharedMemorySize, FA_TOT * 4);
        attr_set = true;
    }

    // launch 0: im2col
    im2col_kernel<<<(BATCH * NPATCH * PCH + 255) / 256, 256>>>(noisy);
    // launch 1: mega cvt
    cvt_all_kernel<<<(WTOTAL / 4 + 511) / 512, 512>>>(W_patch, Wq, Wk, Wv, Wo, Wm1, Wm2, W_final);
    // launches 2-4: timestep chain
    temb_raw_kernel<<<(BATCH * TDIM + 255) / 256, 256>>>(tsteps);
    t1_kernel<<<(BATCH * DIM + 255) / 256, 256>>>(W_t1, b_t1);
    t2_kernel<<<(BATCH * DIM + 255) / 256, 256>>>(W_t2, b_t2);
    // launch 5: patch projection GEMM (profiled by ncu -s 5)
    mma_gemm_kernel<<<dim3(DIM / 128, (BATCH * NPATCH) / 64), 256, 2 * STAGE>>>(
        p_imh, p_iml, p_wh + OFF_PATCH, p_wl + OFF_PATCH,
        p_att, nullptr, nullptr, BATCH * NPATCH, DIM, PCH, nullptr, nullptr, 0, 0);
    // remaining setup
    embed_text_cls_kernel<<<(BATCH * 65 * DIM + 255) / 256, 256>>>(tokens, W_tok, pos_text, cls_tok);
    add_posimg_kernel<<<(BATCH * NPATCH * DIM + 255) / 256, 256>>>(pos_img);
    silu_temb_kernel<<<(BATCH * DIM + 255) / 256, 256>>>();

    int gy = (MROWS + 63) / 64;   // 21

    for (int l = 0; l < NLAYERS; l++) {
        long wqkv_o = OFF_QKV + (long)l * 3 * DD;
        long wo_o   = OFF_WO + (long)l * DD;
        long wm1_o  = OFF_WM1 + (long)l * MLPD * DIM;
        long wm2_o  = OFF_WM2 + (long)l * DIM * MLPD;
        const float* Wada_l = Wada + (long)l * 6 * DIM * DIM;
        const float* bada_l = b_ada + (long)l * 6 * DIM;

        sgemm_kernel<<<dim3(6 * DIM / 64, 1), 256>>>(
            p_t1, Wada_l, p_mod, BATCH, 6 * DIM, DIM, bada_l);

        ln_mod_kernel<<<MROWS, 256>>>(p_x, p_xnh, p_xnl, ln1_g + l * DIM, ln1_b + l * DIM,
                                      p_mod, 0, DIM);

        // fused QKV projection -> g_qkv (fp32)
        mma_gemm_kernel<<<dim3(3 * DIM / 128, gy), 256, 2 * STAGE>>>(
            p_xnh, p_xnl, p_wh + wqkv_o, p_wl + wqkv_o, p_qkv, nullptr, nullptr,
            MROWS, 3 * DIM, DIM, nullptr, nullptr, 0, 0);

        // fused attention (RoPE + scores + softmax + AV) -> bf16 hi/lo o
        flash_attn_kernel<<<dim3(6, BATCH * HEADS), 256, FA_TOT * 4>>>(p_qkv, p_oh, p_ol);

        // x += g_msa * (o @ Wo^T)
        mma_gemm_kernel<<<dim3(DIM / 128, gy), 256, 2 * STAGE>>>(
            p_oh, p_ol, p_wh + wo_o, p_wl + wo_o, p_x, nullptr, nullptr,
            MROWS, DIM, DIM, nullptr, p_mod, 2 * DIM, 2);

        ln_mod_kernel<<<MROWS, 256>>>(p_x, p_xnh, p_xnl, ln2_g + l * DIM, ln2_b + l * DIM,
                                      p_mod, 3 * DIM, 4 * DIM);

        mma_gemm_kernel<<<dim3(MLPD / 128, gy), 256, 2 * STAGE>>>(
            p_xnh, p_xnl, p_wh + wm1_o, p_wl + wm1_o, nullptr, p_hh, p_hl,
            MROWS, MLPD, DIM, nullptr, nullptr, 0, 1);
        mma_gemm_kernel<<<dim3(DIM / 128, gy), 256, 2 * STAGE>>>(
            p_hh, p_hl, p_wh + wm2_o, p_wl + wm2_o, p_x, nullptr, nullptr,
            MROWS, DIM, MLPD, nullptr, p_mod, 5 * DIM, 2);
    }

    // ---- final head ----
    final_ln_kernel<<<BATCH * NPATCH, 256>>>(fn_g, fn_b);
    mma_gemm_kernel<<<dim3(PCH / 128, (BATCH * NPATCH) / 64), 256, 2 * STAGE>>>(
        p_xnh, p_xnl, p_wh + OFF_FIN, p_wl + OFF_FIN, p_h, nullptr, nullptr,
        BATCH * NPATCH, PCH, DIM, b_final, nullptr, 0, 0);
    unpatch_kernel<<<(BATCH * 3 * IMG * IMG + 255) / 256, 256>>>(out);
}

// round 5
// speedup vs baseline: 4.3132x; 1.0825x over previous
#include <cuda_runtime.h>
#include <cuda_bf16.h>
#include <math.h>

// ---------------- problem constants ----------------
#define BATCH   4
#define TEXT    64
#define NTOK    321
#define DIM     1024
#define HEADS   16
#define HD      64
#define MLPD    4096
#define NPATCH  256
#define PCH     768
#define TDIM    256
#define NLAYERS 2
#define VOCAB   50000
#define IMG     256
#define MROWS   (BATCH*NTOK) // 1284
#define DD      (DIM*DIM)

typedef unsigned short u16;
typedef unsigned int u32;

// ---------------- scratch ----------------
__device__ float g_x  [MROWS*DIM];
__device__ float g_qkv[MROWS*3*DIM];
__device__ float g_att[BATCH*NPATCH*DIM];        // patch-embed scratch
__device__ float g_h  [MROWS*MLPD];              // fp32 scratch (final proj out)
__device__ float g_t1raw[BATCH*DIM];             // silu(t1) intermediate
__device__ float g_t1 [BATCH*DIM];               // silu(t_emb)
__device__ float g_mod[BATCH*6*DIM];

// bf16 hi/lo activation buffers
__device__ __align__(16) u16 g_xn_h[MROWS*DIM];
__device__ __align__(16) u16 g_xn_l[MROWS*DIM];
__device__ __align__(16) u16 g_hh  [MROWS*MLPD];
__device__ __align__(16) u16 g_hl  [MROWS*MLPD];
__device__ __align__(16) u16 g_o_h [MROWS*DIM];
__device__ __align__(16) u16 g_o_l [MROWS*DIM];
__device__ __align__(16) u16 g_im_h[BATCH*NPATCH*PCH];
__device__ __align__(16) u16 g_im_l[BATCH*NPATCH*PCH];

// converted weights (hi/lo bf16); QKV interleaved per layer: [3*DIM rows][DIM]
#define OFF_PATCH 0
#define SZ_PATCH  (DIM*PCH)
#define OFF_QKV   (OFF_PATCH+SZ_PATCH)
#define SZ_QKV    (NLAYERS*3*DD)
#define OFF_WO    (OFF_QKV+SZ_QKV)
#define SZ_WO     (NLAYERS*DD)
#define OFF_WM1   (OFF_WO+SZ_WO)
#define SZ_WM     (NLAYERS*MLPD*DIM)
#define OFF_WM2   (OFF_WM1+SZ_WM)
#define OFF_FIN   (OFF_WM2+SZ_WM)
#define SZ_FIN    (PCH*DIM)
#define WTOTAL    (OFF_FIN+SZ_FIN)
__device__ __align__(16) u16 g_w_h[WTOTAL];
__device__ __align__(16) u16 g_w_l[WTOTAL];

// ---------------- helpers ----------------
__device__ __forceinline__ void split_store(float v, u16* h, u16* l, long idx) {
    __nv_bfloat16 hi = __float2bfloat16_rn(v);
    h[idx] = __bfloat16_as_ushort(hi);
    l[idx] = __bfloat16_as_ushort(__float2bfloat16_rn(v - __bfloat162float(hi)));
}

__device__ __forceinline__ u16 bf_hi(float v) {
    return __bfloat16_as_ushort(__float2bfloat16_rn(v));
}

// ---------------- mega weight conversion ----------------
__global__ void cvt_all_kernel(const float* __restrict__ Wp,
                               const float* __restrict__ Wq, const float* __restrict__ Wk,
                               const float* __restrict__ Wv, const float* __restrict__ Wo,
                               const float* __restrict__ Wm1, const float* __restrict__ Wm2,
                               const float* __restrict__ Wf) {
    long q = (long)blockIdx.x * blockDim.x + threadIdx.x;
    long nq = WTOTAL / 4;
    if (q >= nq) return;
    long idx = q * 4;
    const float* src;
    long sofs;
    if (idx < OFF_QKV) { src = Wp; sofs = idx; }
    else if (idx < OFF_WO) {
        long rel = idx - OFF_QKV;
        long l = rel / (3 * (long)DD);
        long r2 = rel % (3 * (long)DD);
        long which = r2 / DD;
        long inner = r2 % DD;
        src = (which == 0) ? Wq : (which == 1) ? Wk : Wv;
        sofs = l * DD + inner;
    } else if (idx < OFF_WM1) { src = Wo; sofs = idx - OFF_WO; }
    else if (idx < OFF_WM2) { src = Wm1; sofs = idx - OFF_WM1; }
    else if (idx < OFF_FIN) { src = Wm2; sofs = idx - OFF_WM2; }
    else { src = Wf; sofs = idx - OFF_FIN; }
    float4 v = *(const float4*)(src + sofs);
    ushort4 h, l4;
    h.x = bf_hi(v.x); h.y = bf_hi(v.y); h.z = bf_hi(v.z); h.w = bf_hi(v.w);
    l4.x = bf_hi(v.x - __bfloat162float(__ushort_as_bfloat16(h.x)));
    l4.y = bf_hi(v.y - __bfloat162float(__ushort_as_bfloat16(h.y)));
    l4.z = bf_hi(v.z - __bfloat162float(__ushort_as_bfloat16(h.z)));
    l4.w = bf_hi(v.w - __bfloat162float(__ushort_as_bfloat16(h.w)));
    *(ushort4*)(g_w_h + idx) = h;
    *(ushort4*)(g_w_l + idx) = l4;
}

// ---------------- embeddings ----------------
__global__ void embed_text_cls_kernel(const int* __restrict__ tokens,
                                      const float* __restrict__ W_tok,
                                      const float* __restrict__ pos_text,
                                      const float* __restrict__ cls_tok) {
    int idx = blockIdx.x * blockDim.x + threadIdx.x;
    if (idx >= BATCH * 65 * DIM) return;
    int d = idx % DIM;
    int t = (idx / DIM) % 65;
    int b = idx / (DIM * 65);
    float v;
    if (t < TEXT) {
        int tok = tokens[b * TEXT + t];
        v = W_tok[(long)d * VOCAB + tok] + pos_text[t * DIM + d];
    } else v = cls_tok[d];
    g_x[(b * NTOK + t) * DIM + d] = v;
}

__global__ void im2col_kernel(const float* __restrict__ img) {
    int idx = blockIdx.x * blockDim.x + threadIdx.x;
    if (idx >= BATCH * NPATCH * PCH) return;
    int c = idx % PCH;
    int p = (idx / PCH) % NPATCH;
    int b = idx / (PCH * NPATCH);
    int ch = c / 256;
    int pr = (c / 16) % 16;
    int pc = c % 16;
    int hp = p / 16, wp = p % 16;
    float v = img[((b * 3 + ch) * IMG + hp * 16 + pr) * IMG + wp * 16 + pc];
    split_store(v, g_im_h, g_im_l, idx);
}

__global__ void add_posimg_kernel(const float* __restrict__ pos_img) {
    int idx = blockIdx.x * blockDim.x + threadIdx.x;
    if (idx >= BATCH * NPATCH * DIM) return;
    int d = idx % DIM;
    int p = (idx / DIM) % NPATCH;
    int b = idx / (DIM * NPATCH);
    g_x[(b * NTOK + 65 + p) * DIM + d] = g_att[idx] + pos_img[p * DIM + d];
}

// ---------------- fused timestep embedding (2 wide kernels) ----------------
// ts_a: temb_raw + t1 (silu). grid (8, BATCH) x 256 threads; warp-per-row dots.
__global__ void ts_a_kernel(const int* __restrict__ tsteps,
                            const float* __restrict__ W_t1, const float* __restrict__ b_t1) {
    __shared__ float sraw[TDIM];
    int b = blockIdx.y;
    int tid = threadIdx.x, lane = tid & 31, warp = tid >> 5;
    {
        int j = tid & 127;
        float f = expf(-logf(10000.0f) * (float)j / 128.0f);
        float a = (float)tsteps[b] * f;
        sraw[tid] = (tid < 128) ? cosf(a) : sinf(a);
    }
    __syncthreads();
#pragma unroll
    for (int r = 0; r < 16; r++) {
        int d = blockIdx.x * 128 + warp * 16 + r;
        const float* w = W_t1 + (long)d * TDIM;
        float s = 0.f;
#pragma unroll
        for (int k8 = 0; k8 < 8; k8++) s += sraw[lane + k8 * 32] * w[lane + k8 * 32];
#pragma unroll
        for (int o = 16; o > 0; o >>= 1) s += __shfl_xor_sync(0xffffffffu, s, o);
        if (lane == 0) {
            s += b_t1[d];
            g_t1raw[b * DIM + d] = s / (1.0f + expf(-s));
        }
    }
}

// ts_b: t2 + silu. grid (16, BATCH) x 256 threads.
__global__ void ts_b_kernel(const float* __restrict__ W_t2, const float* __restrict__ b_t2) {
    __shared__ float st1[DIM];
    int b = blockIdx.y;
    int tid = threadIdx.x, lane = tid & 31, warp = tid >> 5;
#pragma unroll
    for (int i = 0; i < 4; i++) st1[tid + i * 256] = g_t1raw[b * DIM + tid + i * 256];
    __syncthreads();
#pragma unroll
    for (int r = 0; r < 8; r++) {
        int d = blockIdx.x * 64 + warp * 8 + r;
        const float* w = W_t2 + (long)d * DIM;
        float s = 0.f;
#pragma unroll
        for (int k32 = 0; k32 < 32; k32++) s += st1[lane + k32 * 32] * w[lane + k32 * 32];
#pragma unroll
        for (int o = 16; o > 0; o >>= 1) s += __shfl_xor_sync(0xffffffffu, s, o);
        if (lane == 0) {
            s += b_t2[d];
            g_t1[b * DIM + d] = s / (1.0f + expf(-s));
        }
    }
}

// ---------------- scalar SGEMM (adaLN only: M=4) ----------------
__global__ void sgemm_kernel(const float* __restrict__ A, const float* __restrict__ W,
                             float* __restrict__ C, int M, int Nt, int K,
                             const float* __restrict__ bias) {
    __shared__ float As[16][64];
    __shared__ float Ws[16][64];
    int tid = threadIdx.x;
    int row0 = blockIdx.y * 64, col0 = blockIdx.x * 64;
    int tx = tid & 15, ty = tid >> 4;
    int lr = tid >> 2;
    int lk = (tid & 3) * 4;
    float acc[4][4];
#pragma unroll
    for (int i = 0; i < 4; i++)
#pragma unroll
        for (int j = 0; j < 4; j++) acc[i][j] = 0.0f;
    for (int k0 = 0; k0 < K; k0 += 16) {
        int arow = row0 + lr;
        if (arow < M) {
            const float* ap = A + (long)arow * K + k0 + lk;
#pragma unroll
            for (int i = 0; i < 4; i++) As[lk + i][lr] = ap[i];
        } else {
#pragma unroll
            for (int i = 0; i < 4; i++) As[lk + i][lr] = 0.0f;
        }
        const float* wp = W + (long)(col0 + lr) * K + k0 + lk;
#pragma unroll
        for (int i = 0; i < 4; i++) Ws[lk + i][lr] = wp[i];
        __syncthreads();
#pragma unroll
        for (int kk = 0; kk < 16; kk++) {
            float a[4], w[4];
#pragma unroll
            for (int i = 0; i < 4; i++) a[i] = As[kk][ty * 4 + i];
#pragma unroll
            for (int j = 0; j < 4; j++) w[j] = Ws[kk][tx * 4 + j];
#pragma unroll
            for (int i = 0; i < 4; i++)
#pragma unroll
                for (int j = 0; j < 4; j++) acc[i][j] += a[i] * w[j];
        }
        __syncthreads();
    }
#pragma unroll
    for (int i = 0; i < 4; i++) {
        int row = row0 + ty * 4 + i;
        if (row >= M) continue;
#pragma unroll
        for (int j = 0; j < 4; j++) {
            int col = col0 + tx * 4 + j;
            C[(long)row * Nt + col] = acc[i][j] + (bias ? bias[col] : 0.0f);
        }
    }
}

// ---------------- tensor-core GEMM: 128xBN_T tiles, bf16x3, 2-stage cp.async ----------------
__device__ __forceinline__ void cp16(u32 dst, const void* src, bool valid) {
    int sz = valid ? 16 : 0;
    asm volatile("cp.async.ca.shared.global [%0], [%1], 16, %2;\n" :: "r"(dst), "l"(src), "r"(sz));
}
__device__ __forceinline__ void cp_commit() { asm volatile("cp.async.commit_group;\n"); }
__device__ __forceinline__ void cp_wait0() { asm volatile("cp.async.wait_group 0;\n"); }
__device__ __forceinline__ void cp_wait1() { asm volatile("cp.async.wait_group 1;\n"); }

__device__ __forceinline__ void ldsm4(u32& r0, u32& r1, u32& r2, u32& r3, u32 addr) {
    asm volatile("ldmatrix.sync.aligned.m8n8.x4.shared.b16 {%0,%1,%2,%3}, [%4];\n"
                 : "=r"(r0), "=r"(r1), "=r"(r2), "=r"(r3) : "r"(addr));
}

__device__ __forceinline__ void mma16816(float* c, const u32* a, const u32* b) {
    asm volatile(
        "mma.sync.aligned.m16n8k16.row.col.f32.bf16.bf16.f32 "
        "{%0,%1,%2,%3}, {%4,%5,%6,%7}, {%8,%9}, {%0,%1,%2,%3};\n"
        : "+f"(c[0]), "+f"(c[1]), "+f"(c[2]), "+f"(c[3])
        : "r"(a[0]), "r"(a[1]), "r"(a[2]), "r"(a[3]), "r"(b[0]), "r"(b[1]));
}

// epi: 0 = fp32 C (+bias); 1 = gelu -> bf16 hi/lo; 2 = fp32 C += gate*acc
template<int BN_T>
__global__ __launch_bounds__(256) void mma_gemm2_kernel(
        const u16* __restrict__ Ah, const u16* __restrict__ Al,
        const u16* __restrict__ Wh, const u16* __restrict__ Wl,
        float* __restrict__ C, u16* __restrict__ Oh, u16* __restrict__ Ol,
        int M, int Nt, int K,
        const float* __restrict__ bias,
        const float* __restrict__ gate, int gate_ofs, int epi) {
    constexpr int WNC = BN_T / 2;       // cols per warp
    constexpr int NT  = WNC / 8;        // n8 tiles per warp
    constexpr int NTP = WNC / 16;       // n16 ldsm groups per warp
    constexpr u32 SA  = 128 * 80;       // bytes per A half
    constexpr u32 SW  = BN_T * 80;      // bytes per W half
    constexpr u32 WHI = 2 * SA;
    constexpr u32 STG = 2 * SA + 2 * SW;

    extern __shared__ char smem[];
    u32 sbase = (u32)__cvta_generic_to_shared(smem);

    int tid = threadIdx.x, lane = tid & 31, warp = tid >> 5;
    int wm = warp >> 1, wn = warp & 1;
    int row0 = blockIdx.y * 128, col0 = blockIdx.x * BN_T;

    float acc[2][NT][4];
#pragma unroll
    for (int i = 0; i < 2; i++)
#pragma unroll
        for (int j = 0; j < NT; j++)
#pragma unroll
            for (int t = 0; t < 4; t++) acc[i][j][t] = 0.0f;

    u32 a_off = (lane & 15) * 80 + (lane >> 4) * 16;
    u32 w_off = (((lane >> 4) & 1) * 8 + (lane & 7)) * 80 + ((lane >> 3) & 1) * 16;

    auto stage_load = [&](int stage, int k0) {
        u32 sb = sbase + stage * STG;
        constexpr int total = 1024 + 8 * BN_T;
#pragma unroll
        for (int c0 = 0; c0 < total; c0 += 256) {
            int c = c0 + tid;
            const u16* src;
            u32 dofs;
            int idx;
            bool isA;
            if (c < 512)            { src = Ah; dofs = 0;        idx = c;                isA = true; }
            else if (c < 1024)      { src = Al; dofs = SA;       idx = c - 512;          isA = true; }
            else if (c < 1024 + 4 * BN_T) { src = Wh; dofs = WHI;  idx = c - 1024;       isA = false; }
            else                    { src = Wl; dofs = WHI + SW; idx = c - 1024 - 4 * BN_T; isA = false; }
            int row = idx >> 2, q = idx & 3;
            long grow = isA ? (long)(row0 + row) : (long)(col0 + row);
            const void* s = src + grow * K + k0 + q * 8;
            cp16(sb + dofs + row * 80 + q * 16, s, !isA || grow < M);
        }
    };

    int KT = K >> 5;
    stage_load(0, 0);
    cp_commit();

    for (int kt = 0; kt < KT; kt++) {
        if (kt + 1 < KT) {
            stage_load((kt + 1) & 1, (kt + 1) << 5);
            cp_commit();
            cp_wait1();
        } else {
            cp_wait0();
        }
        __syncthreads();

        u32 sb = sbase + (kt & 1) * STG;
#pragma unroll
        for (int s = 0; s < 2; s++) {
            u32 ah[2][4], al[2][4];
#pragma unroll
            for (int mt = 0; mt < 2; mt++) {
                u32 aaddr = sb + (wm * 32 + mt * 16) * 80 + s * 32 + a_off;
                ldsm4(ah[mt][0], ah[mt][1], ah[mt][2], ah[mt][3], aaddr);
                ldsm4(al[mt][0], al[mt][1], al[mt][2], al[mt][3], aaddr + SA);
            }
            u32 bh[NTP][4], bl[NTP][4];
#pragma unroll
            for (int ntp = 0; ntp < NTP; ntp++) {
                u32 waddr = sb + WHI + (wn * WNC + ntp * 16) * 80 + s * 32 + w_off;
                ldsm4(bh[ntp][0], bh[ntp][1], bh[ntp][2], bh[ntp][3], waddr);
                ldsm4(bl[ntp][0], bl[ntp][1], bl[ntp][2], bl[ntp][3], waddr + SW);
            }
#pragma unroll
            for (int mt = 0; mt < 2; mt++)
#pragma unroll
                for (int nt = 0; nt < NT; nt++) {
                    const u32* Bh = &bh[nt >> 1][(nt & 1) * 2];
                    const u32* Bl = &bl[nt >> 1][(nt & 1) * 2];
                    mma16816(acc[mt][nt], ah[mt], Bh);
                    mma16816(acc[mt][nt], ah[mt], Bl);
                    mma16816(acc[mt][nt], al[mt], Bh);
                }
        }
        __syncthreads();
    }

#pragma unroll
    for (int mt = 0; mt < 2; mt++)
#pragma unroll
        for (int nt = 0; nt < NT; nt++)
#pragma unroll
            for (int half = 0; half < 2; half++) {
                int row = row0 + wm * 32 + mt * 16 + (lane >> 2) + half * 8;
                if (row >= M) continue;
#pragma unroll
                for (int jj = 0; jj < 2; jj++) {
                    int col = col0 + wn * WNC + nt * 8 + (lane & 3) * 2 + jj;
                    float v = acc[mt][nt][half * 2 + jj];
                    long idx = (long)row * Nt + col;
                    if (epi == 0) {
                        if (bias) v += bias[col];
                        C[idx] = v;
                    } else if (epi == 1) {
                        float gu = 0.5f * v * (1.0f + erff(v * 0.70710678118654752f));
                        split_store(gu, Oh, Ol, idx);
                    } else {
                        int b = row / NTOK;
                        C[idx] += gate[b * 6 * DIM + gate_ofs + col] * v;
                    }
                }
            }
}

// ---------------- layernorm + adaLN modulation (writes bf16 hi/lo) ----------------
__global__ void ln_mod_kernel(const float* __restrict__ x,
                              u16* __restrict__ outh, u16* __restrict__ outl,
                              const float* __restrict__ g, const float* __restrict__ beta,
                              const float* __restrict__ mod, int sh_ofs, int sc_ofs) {
    int row = blockIdx.x;
    int b = row / NTOK;
    const float* xr = x + (long)row * DIM;
    __shared__ float red[256];
    int tid = threadIdx.x;
    float local[4];
    float s = 0.0f;
#pragma unroll
    for (int i = 0; i < 4; i++) { local[i] = xr[tid + i * 256]; s += local[i]; }
    red[tid] = s; __syncthreads();
    for (int o = 128; o > 0; o >>= 1) { if (tid < o) red[tid] += red[tid + o]; __syncthreads(); }
    float mean = red[0] * (1.0f / DIM);
    __syncthreads();
    float s2 = 0.0f;
#pragma unroll
    for (int i = 0; i < 4; i++) { float d = local[i] - mean; s2 += d * d; }
    red[tid] = s2; __syncthreads();
    for (int o = 128; o > 0; o >>= 1) { if (tid < o) red[tid] += red[tid + o]; __syncthreads(); }
    float inv = rsqrtf(red[0] * (1.0f / DIM) + 1e-5f);
#pragma unroll
    for (int i = 0; i < 4; i++) {
        int d = tid + i * 256;
        float v = (local[i] - mean) * inv * g[d] + beta[d];
        v = v * (1.0f + mod[b * 6 * DIM + sc_ofs + d]) + mod[b * 6 * DIM + sh_ofs + d];
        split_store(v, outh, outl, (long)row * DIM + d);
    }
}

__global__ void final_ln_kernel(const float* __restrict__ g, const float* __restrict__ beta) {
    int p = blockIdx.x % NPATCH;
    int b = blockIdx.x / NPATCH;
    const float* xr = g_x + (long)(b * NTOK + 65 + p) * DIM;
    __shared__ float red[256];
    int tid = threadIdx.x;
    float local[4];
    float s = 0.0f;
#pragma unroll
    for (int i = 0; i < 4; i++) { local[i] = xr[tid + i * 256]; s += local[i]; }
    red[tid] = s; __syncthreads();
    for (int o = 128; o > 0; o >>= 1) { if (tid < o) red[tid] += red[tid + o]; __syncthreads(); }
    float mean = red[0] * (1.0f / DIM);
    __syncthreads();
    float s2 = 0.0f;
#pragma unroll
    for (int i = 0; i < 4; i++) { float d = local[i] - mean; s2 += d * d; }
    red[tid] = s2; __syncthreads();
    for (int o = 128; o > 0; o >>= 1) { if (tid < o) red[tid] += red[tid + o]; __syncthreads(); }
    float inv = rsqrtf(red[0] * (1.0f / DIM) + 1e-5f);
#pragma unroll
    for (int i = 0; i < 4; i++) {
        int d = tid + i * 256;
        float v = (local[i] - mean) * inv * g[d] + beta[d];
        split_store(v, g_xn_h, g_xn_l, (long)blockIdx.x * DIM + d);
    }
}

// ---------------- fused flash attention (RoPE + QK^T + softmax + AV) ----------------
#define FA_SQ  0
#define FA_KV  (64*68)
#define FA_S   (FA_KV + 32*68)
#define FA_TOT (FA_S + 64*352)

__global__ __launch_bounds__(256) void flash_attn_kernel(
        const float* __restrict__ qkv, u16* __restrict__ oh, u16* __restrict__ ol) {
    extern __shared__ float sm[];
    int tile = blockIdx.x;
    int bh = blockIdx.y;
    int h = bh % HEADS, b = bh / HEADS;
    int tid = threadIdx.x, lane = tid & 31, warp = tid >> 5;

    // precise RoPE frequency (d mod 32)
    // freq = 10000^{-(d&31)/32}
    for (int i = tid; i < 64 * 64; i += 256) {
        int r = i >> 6, d = i & 63;
        int grow = tile * 64 + r;
        float v = 0.f;
        if (grow < NTOK) v = qkv[(long)(b * NTOK + grow) * 3072 + h * HD + d];
        sm[FA_SQ + r * 68 + d] = v;
    }
    __syncthreads();
    {
        float tmp[16];
#pragma unroll
        for (int t = 0; t < 16; t++) {
            int i = tid + t * 256;
            int r = i >> 6, d = i & 63;
            int grow = tile * 64 + r;
            float x = sm[FA_SQ + r * 68 + d];
            float pr = (d < 32) ? -sm[FA_SQ + r * 68 + 2 * d + 1] : sm[FA_SQ + r * 68 + 2 * (d - 32)];
            float fr = expf(-(float)(d & 31) * (logf(10000.0f) / 32.0f));
            float c, s;
            sincosf((float)grow * fr, &c, &s);
            tmp[t] = x * c + pr * s;
        }
        __syncthreads();
#pragma unroll
        for (int t = 0; t < 16; t++) {
            int i = tid + t * 256;
            sm[FA_SQ + (i >> 6) * 68 + (i & 63)] = tmp[t];
        }
    }

    for (int c = 0; c < 11; c++) {
        __syncthreads();
        for (int i = tid; i < 32 * 64; i += 256) {
            int j = i >> 6, d = i & 63;
            int krow = c * 32 + j;
            float v = 0.f;
            if (krow < NTOK) v = qkv[(long)(b * NTOK + krow) * 3072 + DIM + h * HD + d];
            sm[FA_KV + j * 68 + d] = v;
        }
        __syncthreads();
        {
            float tmp[8];
#pragma unroll
            for (int t = 0; t < 8; t++) {
                int i = tid + t * 256;
                int j = i >> 6, d = i & 63;
                float x = sm[FA_KV + j * 68 + d];
                float pr = (d < 32) ? -sm[FA_KV + j * 68 + 2 * d + 1] : sm[FA_KV + j * 68 + 2 * (d - 32)];
                float fr = expf(-(float)(d & 31) * (logf(10000.0f) / 32.0f));
                float cc, ss;
                sincosf((float)(c * 32 + j) * fr, &cc, &ss);
                tmp[t] = x * cc + pr * ss;
            }
            __syncthreads();
#pragma unroll
            for (int t = 0; t < 8; t++) {
                int i = tid + t * 256;
                sm[FA_KV + (i >> 6) * 68 + (i & 63)] = tmp[t];
            }
        }
        __syncthreads();
        bool kvalid = (c * 32 + lane) < NTOK;
        const float* kr = &sm[FA_KV + lane * 68];
        float sacc[8];
#pragma unroll
        for (int r8 = 0; r8 < 8; r8++) sacc[r8] = 0.f;
#pragma unroll
        for (int dq = 0; dq < 16; dq++) {
            float4 kv = *(const float4*)(kr + dq * 4);
#pragma unroll
            for (int r8 = 0; r8 < 8; r8++) {
                float4 qv = *(const float4*)&sm[FA_SQ + (warp * 8 + r8) * 68 + dq * 4];
                sacc[r8] += qv.x * kv.x + qv.y * kv.y + qv.z * kv.z + qv.w * kv.w;
            }
        }
#pragma unroll
        for (int r8 = 0; r8 < 8; r8++) {
            int r = warp * 8 + r8;
            sm[FA_S + r * 352 + c * 32 + lane] = kvalid ? sacc[r8] * 0.125f : -1e30f;
        }
    }

    float invr[8];
#pragma unroll
    for (int r8 = 0; r8 < 8; r8++) {
        float* Sr = &sm[FA_S + (warp * 8 + r8) * 352];
        float mx = -1e30f;
#pragma unroll
        for (int k = 0; k < 11; k++) mx = fmaxf(mx, Sr[lane + k * 32]);
#pragma unroll
        for (int o = 16; o > 0; o >>= 1) mx = fmaxf(mx, __shfl_xor_sync(0xffffffffu, mx, o));
        float sum = 0.f;
#pragma unroll
        for (int k = 0; k < 11; k++) {
            float e = __expf(Sr[lane + k * 32] - mx);
            Sr[lane + k * 32] = e;
            sum += e;
        }
#pragma unroll
        for (int o = 16; o > 0; o >>= 1) sum += __shfl_xor_sync(0xffffffffu, sum, o);
        invr[r8] = 1.0f / sum;
    }

    float acc0[8], acc1[8];
#pragma unroll
    for (int r8 = 0; r8 < 8; r8++) { acc0[r8] = 0.f; acc1[r8] = 0.f; }
    for (int c = 0; c < 11; c++) {
        __syncthreads();
        for (int i = tid; i < 32 * 64; i += 256) {
            int j = i >> 6, d = i & 63;
            int vrow = c * 32 + j;
            float v = 0.f;
            if (vrow < NTOK) v = qkv[(long)(b * NTOK + vrow) * 3072 + 2 * DIM + h * HD + d];
            sm[FA_KV + j * 68 + d] = v;
        }
        __syncthreads();
#pragma unroll
        for (int jq = 0; jq < 8; jq++) {
            float v0[4], v1[4];
#pragma unroll
            for (int t = 0; t < 4; t++) {
                v0[t] = sm[FA_KV + (jq * 4 + t) * 68 + lane];
                v1[t] = sm[FA_KV + (jq * 4 + t) * 68 + lane + 32];
            }
#pragma unroll
            for (int r8 = 0; r8 < 8; r8++) {
                float4 p = *(const float4*)&sm[FA_S + (warp * 8 + r8) * 352 + c * 32 + jq * 4];
                acc0[r8] += p.x * v0[0] + p.y * v0[1] + p.z * v0[2] + p.w * v0[3];
                acc1[r8] += p.x * v1[0] + p.y * v1[1] + p.z * v1[2] + p.w * v1[3];
            }
        }
    }

#pragma unroll
    for (int r8 = 0; r8 < 8; r8++) {
        int grow = tile * 64 + warp * 8 + r8;
        if (grow >= NTOK) continue;
        long o = (long)(b * NTOK + grow) * DIM + h * HD + lane;
        split_store(acc0[r8] * invr[r8], oh, ol, o);
        split_store(acc1[r8] * invr[r8], oh, ol, o + 32);
    }
}

// ---------------- output unpatchify ----------------
__global__ void unpatch_kernel(float* __restrict__ out) {
    int idx = blockIdx.x * blockDim.x + threadIdx.x;
    if (idx >= BATCH * 3 * IMG * IMG) return;
    int c_img = idx % IMG;
    int r_img = (idx / IMG) % IMG;
    int ch = (idx / (IMG * IMG)) % 3;
    int b = idx / (3 * IMG * IMG);
    int hp = r_img / 16, pr = r_img % 16;
    int wp = c_img / 16, pc = c_img % 16;
    out[idx] = g_h[(long)(b * NPATCH + hp * 16 + wp) * PCH + ch * 256 + pr * 16 + pc];
}

// ---------------- host launch ----------------
static void* symaddr_raw(const void* sym) {
    void* p = nullptr;
    cudaGetSymbolAddress(&p, sym);
    return p;
}

#define SMEM128 (2 * (2 * 128 * 80 + 2 * 128 * 80))   // 81920
#define SMEM64  (2 * (2 * 128 * 80 + 2 * 64 * 80))    // 61440

extern "C" void kernel_launch(void* const* d_in, const int* in_sizes, int n_in,
                              void* d_out, int out_size) {
    const float* noisy    = (const float*)d_in[0];
    const int*   tokens   = (const int*)  d_in[1];
    const int*   tsteps   = (const int*)  d_in[2];
    const float* W_tok    = (const float*)d_in[3];
    const float* pos_text = (const float*)d_in[4];
    const float* W_patch  = (const float*)d_in[5];
    const float* pos_img  = (const float*)d_in[6];
    const float* cls_tok  = (const float*)d_in[7];
    const float* W_t1     = (const float*)d_in[8];
    const float* b_t1     = (const float*)d_in[9];
    const float* W_t2     = (const float*)d_in[10];
    const float* b_t2     = (const float*)d_in[11];
    const float* ln1_g    = (const float*)d_in[12];
    const float* ln1_b    = (const float*)d_in[13];
    const float* Wq       = (const float*)d_in[14];
    const float* Wk       = (const float*)d_in[15];
    const float* Wv       = (const float*)d_in[16];
    const float* Wo       = (const float*)d_in[17];
    const float* ln2_g    = (const float*)d_in[18];
    const float* ln2_b    = (const float*)d_in[19];
    const float* Wm1      = (const float*)d_in[20];
    const float* Wm2      = (const float*)d_in[21];
    const float* Wada     = (const float*)d_in[22];
    const float* b_ada    = (const float*)d_in[23];
    const float* fn_g     = (const float*)d_in[24];
    const float* fn_b     = (const float*)d_in[25];
    const float* W_final  = (const float*)d_in[26];
    const float* b_final  = (const float*)d_in[27];
    float* out = (float*)d_out;

    float* p_x    = (float*)symaddr_raw(g_x);
    float* p_qkv  = (float*)symaddr_raw(g_qkv);
    float* p_att  = (float*)symaddr_raw(g_att);
    float* p_h    = (float*)symaddr_raw(g_h);
    float* p_t1   = (float*)symaddr_raw(g_t1);
    float* p_mod  = (float*)symaddr_raw(g_mod);
    u16* p_wh     = (u16*)symaddr_raw(g_w_h);
    u16* p_wl     = (u16*)symaddr_raw(g_w_l);
    u16* p_xnh    = (u16*)symaddr_raw(g_xn_h);
    u16* p_xnl    = (u16*)symaddr_raw(g_xn_l);
    u16* p_hh     = (u16*)symaddr_raw(g_hh);
    u16* p_hl     = (u16*)symaddr_raw(g_hl);
    u16* p_oh     = (u16*)symaddr_raw(g_o_h);
    u16* p_ol     = (u16*)symaddr_raw(g_o_l);
    u16* p_imh    = (u16*)symaddr_raw(g_im_h);
    u16* p_iml    = (u16*)symaddr_raw(g_im_l);

    static bool attr_set = false;
    if (!attr_set) {
        cudaFuncSetAttribute(mma_gemm2_kernel<128>, cudaFuncAttributeMaxDynamicSharedMemorySize, SMEM128);
        cudaFuncSetAttribute(mma_gemm2_kernel<64>, cudaFuncAttributeMaxDynamicSharedMemorySize, SMEM64);
        cudaFuncSetAttribute(flash_attn_kernel, cudaFuncAttributeMaxDynamicSharedMemorySize, FA_TOT * 4);
        attr_set = true;
    }

    im2col_kernel<<<(BATCH * NPATCH * PCH + 255) / 256, 256>>>(noisy);
    cvt_all_kernel<<<(WTOTAL / 4 + 511) / 512, 512>>>(W_patch, Wq, Wk, Wv, Wo, Wm1, Wm2, W_final);
    ts_a_kernel<<<dim3(8, BATCH), 256>>>(tsteps, W_t1, b_t1);
    ts_b_kernel<<<dim3(16, BATCH), 256>>>(W_t2, b_t2);
    // patch projection: (1024 x 768) @ W_patch^T -> (1024 x 1024)
    mma_gemm2_kernel<64><<<dim3(DIM / 64, 8), 256, SMEM64>>>(
        p_imh, p_iml, p_wh + OFF_PATCH, p_wl + OFF_PATCH,
        p_att, nullptr, nullptr, BATCH * NPATCH, DIM, PCH, nullptr, nullptr, 0, 0);
    embed_text_cls_kernel<<<(BATCH * 65 * DIM + 255) / 256, 256>>>(tokens, W_tok, pos_text, cls_tok);
    add_posimg_kernel<<<(BATCH * NPATCH * DIM + 255) / 256, 256>>>(pos_img);

    int gy = (MROWS + 127) / 128;   // 11

    for (int l = 0; l < NLAYERS; l++) {
        long wqkv_o = OFF_QKV + (long)l * 3 * DD;
        long wo_o   = OFF_WO + (long)l * DD;
        long wm1_o  = OFF_WM1 + (long)l * MLPD * DIM;
        long wm2_o  = OFF_WM2 + (long)l * DIM * MLPD;
        const float* Wada_l = Wada + (long)l * 6 * DIM * DIM;
        const float* bada_l = b_ada + (long)l * 6 * DIM;

        sgemm_kernel<<<dim3(6 * DIM / 64, 1), 256>>>(
            p_t1, Wada_l, p_mod, BATCH, 6 * DIM, DIM, bada_l);

        ln_mod_kernel<<<MROWS, 256>>>(p_x, p_xnh, p_xnl, ln1_g + l * DIM, ln1_b + l * DIM,
                                      p_mod, 0, DIM);

        // fused QKV projection -> g_qkv (fp32)
        mma_gemm2_kernel<128><<<dim3(3 * DIM / 128, gy), 256, SMEM128>>>(
            p_xnh, p_xnl, p_wh + wqkv_o, p_wl + wqkv_o, p_qkv, nullptr, nullptr,
            MROWS, 3 * DIM, DIM, nullptr, nullptr, 0, 0);

        // fused attention
        flash_attn_kernel<<<dim3(6, BATCH * HEADS), 256, FA_TOT * 4>>>(p_qkv, p_oh, p_ol);

        // x += g_msa * (o @ Wo^T)
        mma_gemm2_kernel<64><<<dim3(DIM / 64, gy), 256, SMEM64>>>(
            p_oh, p_ol, p_wh + wo_o, p_wl + wo_o, p_x, nullptr, nullptr,
            MROWS, DIM, DIM, nullptr, p_mod, 2 * DIM, 2);

        ln_mod_kernel<<<MROWS, 256>>>(p_x, p_xnh, p_xnl, ln2_g + l * DIM, ln2_b + l * DIM,
                                      p_mod, 3 * DIM, 4 * DIM);

        mma_gemm2_kernel<128><<<dim3(MLPD / 128, gy), 256, SMEM128>>>(
            p_xnh, p_xnl, p_wh + wm1_o, p_wl + wm1_o, nullptr, p_hh, p_hl,
            MROWS, MLPD, DIM, nullptr, nullptr, 0, 1);
        mma_gemm2_kernel<64><<<dim3(DIM / 64, gy), 256, SMEM64>>>(
            p_hh, p_hl, p_wh + wm2_o, p_wl + wm2_o, p_x, nullptr, nullptr,
            MROWS, DIM, MLPD, nullptr, p_mod, 5 * DIM, 2);
    }

    // ---- final head ----
    final_ln_kernel<<<BATCH * NPATCH, 256>>>(fn_g, fn_b);
    mma_gemm2_kernel<64><<<dim3(PCH / 64, 8), 256, SMEM64>>>(
        p_xnh, p_xnl, p_wh + OFF_FIN, p_wl + OFF_FIN, p_h, nullptr, nullptr,
        BATCH * NPATCH, PCH, DIM, b_final, nullptr, 0, 0);
    unpatch_kernel<<<(BATCH * 3 * IMG * IMG + 255) / 256, 256>>>(out);
}

// round 6
// speedup vs baseline: 4.8597x; 1.1267x over previous
#include <cuda_runtime.h>
#include <cuda_bf16.h>
#include <math.h>

// ---------------- problem constants ----------------
#define BATCH   4
#define TEXT    64
#define NTOK    321
#define DIM     1024
#define HEADS   16
#define HD      64
#define MLPD    4096
#define NPATCH  256
#define PCH     768
#define TDIM    256
#define NLAYERS 2
#define VOCAB   50000
#define IMG     256
#define MROWS   (BATCH*NTOK) // 1284
#define DD      (DIM*DIM)
#define NPAD    384          // padded token count for rope table

typedef unsigned short u16;
typedef unsigned int u32;

// ---------------- scratch ----------------
__device__ float g_x  [MROWS*DIM];
__device__ float g_qkv[MROWS*3*DIM];
__device__ float g_att[BATCH*NPATCH*DIM];        // patch-embed scratch
__device__ float g_h  [MROWS*MLPD];              // fp32 scratch (final proj out)
__device__ float g_t1raw[BATCH*DIM];
__device__ float g_t1 [BATCH*DIM];
__device__ float g_mod[BATCH*6*DIM];
__device__ float g_ropec[NPAD*HD];
__device__ float g_ropes[NPAD*HD];

// bf16 hi/lo activation buffers
__device__ __align__(16) u16 g_xn_h[MROWS*DIM];
__device__ __align__(16) u16 g_xn_l[MROWS*DIM];
__device__ __align__(16) u16 g_hh  [MROWS*MLPD];
__device__ __align__(16) u16 g_hl  [MROWS*MLPD];
__device__ __align__(16) u16 g_o_h [MROWS*DIM];
__device__ __align__(16) u16 g_o_l [MROWS*DIM];
__device__ __align__(16) u16 g_im_h[BATCH*NPATCH*PCH];
__device__ __align__(16) u16 g_im_l[BATCH*NPATCH*PCH];

// converted weights (hi/lo bf16)
#define OFF_PATCH 0
#define SZ_PATCH  (DIM*PCH)
#define OFF_QKV   (OFF_PATCH+SZ_PATCH)
#define SZ_QKV    (NLAYERS*3*DD)
#define OFF_WO    (OFF_QKV+SZ_QKV)
#define SZ_WO     (NLAYERS*DD)
#define OFF_WM1   (OFF_WO+SZ_WO)
#define SZ_WM     (NLAYERS*MLPD*DIM)
#define OFF_WM2   (OFF_WM1+SZ_WM)
#define OFF_FIN   (OFF_WM2+SZ_WM)
#define SZ_FIN    (PCH*DIM)
#define WTOTAL    (OFF_FIN+SZ_FIN)
__device__ __align__(16) u16 g_w_h[WTOTAL];
__device__ __align__(16) u16 g_w_l[WTOTAL];

// ---------------- helpers ----------------
__device__ __forceinline__ void split_store(float v, u16* h, u16* l, long idx) {
    __nv_bfloat16 hi = __float2bfloat16_rn(v);
    h[idx] = __bfloat16_as_ushort(hi);
    l[idx] = __bfloat16_as_ushort(__float2bfloat16_rn(v - __bfloat162float(hi)));
}

__device__ __forceinline__ u16 bf_hi(float v) {
    return __bfloat16_as_ushort(__float2bfloat16_rn(v));
}

// ---------------- RoPE tables (double precision; exact) ----------------
__global__ void rope_table_kernel() {
    int idx = blockIdx.x * blockDim.x + threadIdx.x;
    if (idx >= NPAD * HD) return;
    int d = idx & 63, n = idx >> 6;
    double fr = pow(10000.0, -((double)(d & 31)) / 32.0);
    double a = (double)n * fr;
    g_ropec[idx] = (float)cos(a);
    g_ropes[idx] = (float)sin(a);
}

// ---------------- mega weight conversion ----------------
__global__ void cvt_all_kernel(const float* __restrict__ Wp,
                               const float* __restrict__ Wq, const float* __restrict__ Wk,
                               const float* __restrict__ Wv, const float* __restrict__ Wo,
                               const float* __restrict__ Wm1, const float* __restrict__ Wm2,
                               const float* __restrict__ Wf) {
    long q = (long)blockIdx.x * blockDim.x + threadIdx.x;
    long nq = WTOTAL / 4;
    if (q >= nq) return;
    long idx = q * 4;
    const float* src;
    long sofs;
    if (idx < OFF_QKV) { src = Wp; sofs = idx; }
    else if (idx < OFF_WO) {
        long rel = idx - OFF_QKV;
        long l = rel / (3 * (long)DD);
        long r2 = rel % (3 * (long)DD);
        long which = r2 / DD;
        long inner = r2 % DD;
        src = (which == 0) ? Wq : (which == 1) ? Wk : Wv;
        sofs = l * DD + inner;
    } else if (idx < OFF_WM1) { src = Wo; sofs = idx - OFF_WO; }
    else if (idx < OFF_WM2) { src = Wm1; sofs = idx - OFF_WM1; }
    else if (idx < OFF_FIN) { src = Wm2; sofs = idx - OFF_WM2; }
    else { src = Wf; sofs = idx - OFF_FIN; }
    float4 v = *(const float4*)(src + sofs);
    ushort4 h, l4;
    h.x = bf_hi(v.x); h.y = bf_hi(v.y); h.z = bf_hi(v.z); h.w = bf_hi(v.w);
    l4.x = bf_hi(v.x - __bfloat162float(__ushort_as_bfloat16(h.x)));
    l4.y = bf_hi(v.y - __bfloat162float(__ushort_as_bfloat16(h.y)));
    l4.z = bf_hi(v.z - __bfloat162float(__ushort_as_bfloat16(h.z)));
    l4.w = bf_hi(v.w - __bfloat162float(__ushort_as_bfloat16(h.w)));
    *(ushort4*)(g_w_h + idx) = h;
    *(ushort4*)(g_w_l + idx) = l4;
}

// ---------------- embeddings ----------------
__global__ void embed_text_cls_kernel(const int* __restrict__ tokens,
                                      const float* __restrict__ W_tok,
                                      const float* __restrict__ pos_text,
                                      const float* __restrict__ cls_tok) {
    int idx = blockIdx.x * blockDim.x + threadIdx.x;
    if (idx >= BATCH * 65 * DIM) return;
    int d = idx % DIM;
    int t = (idx / DIM) % 65;
    int b = idx / (DIM * 65);
    float v;
    if (t < TEXT) {
        int tok = tokens[b * TEXT + t];
        v = W_tok[(long)d * VOCAB + tok] + pos_text[t * DIM + d];
    } else v = cls_tok[d];
    g_x[(b * NTOK + t) * DIM + d] = v;
}

__global__ void im2col_kernel(const float* __restrict__ img) {
    int idx = blockIdx.x * blockDim.x + threadIdx.x;
    if (idx >= BATCH * NPATCH * PCH) return;
    int c = idx % PCH;
    int p = (idx / PCH) % NPATCH;
    int b = idx / (PCH * NPATCH);
    int ch = c / 256;
    int pr = (c / 16) % 16;
    int pc = c % 16;
    int hp = p / 16, wp = p % 16;
    float v = img[((b * 3 + ch) * IMG + hp * 16 + pr) * IMG + wp * 16 + pc];
    split_store(v, g_im_h, g_im_l, idx);
}

__global__ void add_posimg_kernel(const float* __restrict__ pos_img) {
    int idx = blockIdx.x * blockDim.x + threadIdx.x;
    if (idx >= BATCH * NPATCH * DIM) return;
    int d = idx % DIM;
    int p = (idx / DIM) % NPATCH;
    int b = idx / (DIM * NPATCH);
    g_x[(b * NTOK + 65 + p) * DIM + d] = g_att[idx] + pos_img[p * DIM + d];
}

// ---------------- timestep embedding (warp-per-row) ----------------
__global__ void ts_a_kernel(const int* __restrict__ tsteps,
                            const float* __restrict__ W_t1, const float* __restrict__ b_t1) {
    __shared__ float sraw[TDIM];
    int b = blockIdx.y;
    int tid = threadIdx.x, lane = tid & 31, warp = tid >> 5;
    {
        int j = tid & 127;
        float f = expf(-logf(10000.0f) * (float)j / 128.0f);
        float a = (float)tsteps[b] * f;
        sraw[tid] = (tid < 128) ? cosf(a) : sinf(a);
    }
    __syncthreads();
#pragma unroll
    for (int r = 0; r < 4; r++) {
        int d = blockIdx.x * 32 + warp * 4 + r;
        const float4* w = (const float4*)(W_t1 + (long)d * TDIM);
        const float4* a4 = (const float4*)sraw;
        float s = 0.f;
#pragma unroll
        for (int it = 0; it < 2; it++) {
            float4 wv = w[it * 32 + lane];
            float4 av = a4[it * 32 + lane];
            s += wv.x * av.x + wv.y * av.y + wv.z * av.z + wv.w * av.w;
        }
#pragma unroll
        for (int o = 16; o > 0; o >>= 1) s += __shfl_xor_sync(0xffffffffu, s, o);
        if (lane == 0) {
            s += b_t1[d];
            g_t1raw[b * DIM + d] = s / (1.0f + expf(-s));
        }
    }
}

__global__ void ts_b_kernel(const float* __restrict__ W_t2, const float* __restrict__ b_t2) {
    int b = blockIdx.y;
    int tid = threadIdx.x, lane = tid & 31, warp = tid >> 5;
    const float4* a4 = (const float4*)(g_t1raw + b * DIM);
#pragma unroll
    for (int r = 0; r < 4; r++) {
        int d = blockIdx.x * 32 + warp * 4 + r;
        const float4* w = (const float4*)(W_t2 + (long)d * DIM);
        float s = 0.f;
#pragma unroll
        for (int it = 0; it < 8; it++) {
            float4 wv = w[it * 32 + lane];
            float4 av = a4[it * 32 + lane];
            s += wv.x * av.x + wv.y * av.y + wv.z * av.z + wv.w * av.w;
        }
#pragma unroll
        for (int o = 16; o > 0; o >>= 1) s += __shfl_xor_sync(0xffffffffu, s, o);
        if (lane == 0) {
            s += b_t2[d];
            g_t1[b * DIM + d] = s / (1.0f + expf(-s));
        }
    }
}

// ---------------- adaLN modulation (warp-per-row, all 4 batches) ----------------
__global__ void ada_kernel(const float* __restrict__ W, const float* __restrict__ bias) {
    int tid = threadIdx.x, lane = tid & 31, warp = tid >> 5;
#pragma unroll
    for (int r = 0; r < 4; r++) {
        int row = blockIdx.x * 32 + warp * 4 + r;
        const float4* w = (const float4*)(W + (long)row * DIM);
        float a0 = 0.f, a1 = 0.f, a2 = 0.f, a3 = 0.f;
#pragma unroll
        for (int it = 0; it < 8; it++) {
            float4 wv = w[it * 32 + lane];
            float4 v0 = *(const float4*)&g_t1[0 * DIM + it * 128 + lane * 4];
            float4 v1 = *(const float4*)&g_t1[1 * DIM + it * 128 + lane * 4];
            float4 v2 = *(const float4*)&g_t1[2 * DIM + it * 128 + lane * 4];
            float4 v3 = *(const float4*)&g_t1[3 * DIM + it * 128 + lane * 4];
            a0 += wv.x * v0.x + wv.y * v0.y + wv.z * v0.z + wv.w * v0.w;
            a1 += wv.x * v1.x + wv.y * v1.y + wv.z * v1.z + wv.w * v1.w;
            a2 += wv.x * v2.x + wv.y * v2.y + wv.z * v2.z + wv.w * v2.w;
            a3 += wv.x * v3.x + wv.y * v3.y + wv.z * v3.z + wv.w * v3.w;
        }
#pragma unroll
        for (int o = 16; o > 0; o >>= 1) {
            a0 += __shfl_xor_sync(0xffffffffu, a0, o);
            a1 += __shfl_xor_sync(0xffffffffu, a1, o);
            a2 += __shfl_xor_sync(0xffffffffu, a2, o);
            a3 += __shfl_xor_sync(0xffffffffu, a3, o);
        }
        if (lane == 0) {
            float bs = bias[row];
            g_mod[0 * 6 * DIM + row] = a0 + bs;
            g_mod[1 * 6 * DIM + row] = a1 + bs;
            g_mod[2 * 6 * DIM + row] = a2 + bs;
            g_mod[3 * 6 * DIM + row] = a3 + bs;
        }
    }
}

// ---------------- tensor-core GEMM: 128xBN_T tiles, bf16x3, 2-stage cp.async ----------------
__device__ __forceinline__ void cp16(u32 dst, const void* src, bool valid) {
    int sz = valid ? 16 : 0;
    asm volatile("cp.async.ca.shared.global [%0], [%1], 16, %2;\n" :: "r"(dst), "l"(src), "r"(sz));
}
__device__ __forceinline__ void cp_commit() { asm volatile("cp.async.commit_group;\n"); }
__device__ __forceinline__ void cp_wait0() { asm volatile("cp.async.wait_group 0;\n"); }
__device__ __forceinline__ void cp_wait1() { asm volatile("cp.async.wait_group 1;\n"); }

__device__ __forceinline__ void ldsm4(u32& r0, u32& r1, u32& r2, u32& r3, u32 addr) {
    asm volatile("ldmatrix.sync.aligned.m8n8.x4.shared.b16 {%0,%1,%2,%3}, [%4];\n"
                 : "=r"(r0), "=r"(r1), "=r"(r2), "=r"(r3) : "r"(addr));
}

__device__ __forceinline__ void mma16816(float* c, const u32* a, const u32* b) {
    asm volatile(
        "mma.sync.aligned.m16n8k16.row.col.f32.bf16.bf16.f32 "
        "{%0,%1,%2,%3}, {%4,%5,%6,%7}, {%8,%9}, {%0,%1,%2,%3};\n"
        : "+f"(c[0]), "+f"(c[1]), "+f"(c[2]), "+f"(c[3])
        : "r"(a[0]), "r"(a[1]), "r"(a[2]), "r"(a[3]), "r"(b[0]), "r"(b[1]));
}

// epi: 0 = fp32 C (+bias); 1 = gelu -> bf16 hi/lo; 2 = fp32 C += gate*acc
template<int BN_T>
__global__ __launch_bounds__(256) void mma_gemm2_kernel(
        const u16* __restrict__ Ah, const u16* __restrict__ Al,
        const u16* __restrict__ Wh, const u16* __restrict__ Wl,
        float* __restrict__ C, u16* __restrict__ Oh, u16* __restrict__ Ol,
        int M, int Nt, int K,
        const float* __restrict__ bias,
        const float* __restrict__ gate, int gate_ofs, int epi) {
    constexpr int WNC = BN_T / 2;
    constexpr int NT  = WNC / 8;
    constexpr int NTP = WNC / 16;
    constexpr u32 SA  = 128 * 80;
    constexpr u32 SW  = BN_T * 80;
    constexpr u32 WHI = 2 * SA;
    constexpr u32 STG = 2 * SA + 2 * SW;

    extern __shared__ char smem[];
    u32 sbase = (u32)__cvta_generic_to_shared(smem);

    int tid = threadIdx.x, lane = tid & 31, warp = tid >> 5;
    int wm = warp >> 1, wn = warp & 1;
    int row0 = blockIdx.y * 128, col0 = blockIdx.x * BN_T;

    float acc[2][NT][4];
#pragma unroll
    for (int i = 0; i < 2; i++)
#pragma unroll
        for (int j = 0; j < NT; j++)
#pragma unroll
            for (int t = 0; t < 4; t++) acc[i][j][t] = 0.0f;

    u32 a_off = (lane & 15) * 80 + (lane >> 4) * 16;
    u32 w_off = (((lane >> 4) & 1) * 8 + (lane & 7)) * 80 + ((lane >> 3) & 1) * 16;

    auto stage_load = [&](int stage, int k0) {
        u32 sb = sbase + stage * STG;
        constexpr int total = 1024 + 8 * BN_T;
#pragma unroll
        for (int c0 = 0; c0 < total; c0 += 256) {
            int c = c0 + tid;
            const u16* src;
            u32 dofs;
            int idx;
            bool isA;
            if (c < 512)            { src = Ah; dofs = 0;        idx = c;                isA = true; }
            else if (c < 1024)      { src = Al; dofs = SA;       idx = c - 512;          isA = true; }
            else if (c < 1024 + 4 * BN_T) { src = Wh; dofs = WHI;  idx = c - 1024;       isA = false; }
            else                    { src = Wl; dofs = WHI + SW; idx = c - 1024 - 4 * BN_T; isA = false; }
            int row = idx >> 2, q = idx & 3;
            long grow = isA ? (long)(row0 + row) : (long)(col0 + row);
            const void* s = src + grow * K + k0 + q * 8;
            cp16(sb + dofs + row * 80 + q * 16, s, !isA || grow < M);
        }
    };

    int KT = K >> 5;
    stage_load(0, 0);
    cp_commit();

    for (int kt = 0; kt < KT; kt++) {
        if (kt + 1 < KT) {
            stage_load((kt + 1) & 1, (kt + 1) << 5);
            cp_commit();
            cp_wait1();
        } else {
            cp_wait0();
        }
        __syncthreads();

        u32 sb = sbase + (kt & 1) * STG;
#pragma unroll
        for (int s = 0; s < 2; s++) {
            u32 ah[2][4], al[2][4];
#pragma unroll
            for (int mt = 0; mt < 2; mt++) {
                u32 aaddr = sb + (wm * 32 + mt * 16) * 80 + s * 32 + a_off;
                ldsm4(ah[mt][0], ah[mt][1], ah[mt][2], ah[mt][3], aaddr);
                ldsm4(al[mt][0], al[mt][1], al[mt][2], al[mt][3], aaddr + SA);
            }
            u32 bh[NTP][4], bl[NTP][4];
#pragma unroll
            for (int ntp = 0; ntp < NTP; ntp++) {
                u32 waddr = sb + WHI + (wn * WNC + ntp * 16) * 80 + s * 32 + w_off;
                ldsm4(bh[ntp][0], bh[ntp][1], bh[ntp][2], bh[ntp][3], waddr);
                ldsm4(bl[ntp][0], bl[ntp][1], bl[ntp][2], bl[ntp][3], waddr + SW);
            }
#pragma unroll
            for (int mt = 0; mt < 2; mt++)
#pragma unroll
                for (int nt = 0; nt < NT; nt++) {
                    const u32* Bh = &bh[nt >> 1][(nt & 1) * 2];
                    const u32* Bl = &bl[nt >> 1][(nt & 1) * 2];
                    mma16816(acc[mt][nt], ah[mt], Bh);
                    mma16816(acc[mt][nt], ah[mt], Bl);
                    mma16816(acc[mt][nt], al[mt], Bh);
                }
        }
        __syncthreads();
    }

#pragma unroll
    for (int mt = 0; mt < 2; mt++)
#pragma unroll
        for (int nt = 0; nt < NT; nt++)
#pragma unroll
            for (int half = 0; half < 2; half++) {
                int row = row0 + wm * 32 + mt * 16 + (lane >> 2) + half * 8;
                if (row >= M) continue;
#pragma unroll
                for (int jj = 0; jj < 2; jj++) {
                    int col = col0 + wn * WNC + nt * 8 + (lane & 3) * 2 + jj;
                    float v = acc[mt][nt][half * 2 + jj];
                    long idx = (long)row * Nt + col;
                    if (epi == 0) {
                        if (bias) v += bias[col];
                        C[idx] = v;
                    } else if (epi == 1) {
                        float gu = 0.5f * v * (1.0f + erff(v * 0.70710678118654752f));
                        split_store(gu, Oh, Ol, idx);
                    } else {
                        int b = row / NTOK;
                        C[idx] += gate[b * 6 * DIM + gate_ofs + col] * v;
                    }
                }
            }
}

// ---------------- layernorm + adaLN modulation ----------------
__global__ void ln_mod_kernel(const float* __restrict__ x,
                              u16* __restrict__ outh, u16* __restrict__ outl,
                              const float* __restrict__ g, const float* __restrict__ beta,
                              const float* __restrict__ mod, int sh_ofs, int sc_ofs) {
    int row = blockIdx.x;
    int b = row / NTOK;
    const float* xr = x + (long)row * DIM;
    __shared__ float red[256];
    int tid = threadIdx.x;
    float local[4];
    float s = 0.0f;
#pragma unroll
    for (int i = 0; i < 4; i++) { local[i] = xr[tid + i * 256]; s += local[i]; }
    red[tid] = s; __syncthreads();
    for (int o = 128; o > 0; o >>= 1) { if (tid < o) red[tid] += red[tid + o]; __syncthreads(); }
    float mean = red[0] * (1.0f / DIM);
    __syncthreads();
    float s2 = 0.0f;
#pragma unroll
    for (int i = 0; i < 4; i++) { float d = local[i] - mean; s2 += d * d; }
    red[tid] = s2; __syncthreads();
    for (int o = 128; o > 0; o >>= 1) { if (tid < o) red[tid] += red[tid + o]; __syncthreads(); }
    float inv = rsqrtf(red[0] * (1.0f / DIM) + 1e-5f);
#pragma unroll
    for (int i = 0; i < 4; i++) {
        int d = tid + i * 256;
        float v = (local[i] - mean) * inv * g[d] + beta[d];
        v = v * (1.0f + mod[b * 6 * DIM + sc_ofs + d]) + mod[b * 6 * DIM + sh_ofs + d];
        split_store(v, outh, outl, (long)row * DIM + d);
    }
}

__global__ void final_ln_kernel(const float* __restrict__ g, const float* __restrict__ beta) {
    int p = blockIdx.x % NPATCH;
    int b = blockIdx.x / NPATCH;
    const float* xr = g_x + (long)(b * NTOK + 65 + p) * DIM;
    __shared__ float red[256];
    int tid = threadIdx.x;
    float local[4];
    float s = 0.0f;
#pragma unroll
    for (int i = 0; i < 4; i++) { local[i] = xr[tid + i * 256]; s += local[i]; }
    red[tid] = s; __syncthreads();
    for (int o = 128; o > 0; o >>= 1) { if (tid < o) red[tid] += red[tid + o]; __syncthreads(); }
    float mean = red[0] * (1.0f / DIM);
    __syncthreads();
    float s2 = 0.0f;
#pragma unroll
    for (int i = 0; i < 4; i++) { float d = local[i] - mean; s2 += d * d; }
    red[tid] = s2; __syncthreads();
    for (int o = 128; o > 0; o >>= 1) { if (tid < o) red[tid] += red[tid + o]; __syncthreads(); }
    float inv = rsqrtf(red[0] * (1.0f / DIM) + 1e-5f);
#pragma unroll
    for (int i = 0; i < 4; i++) {
        int d = tid + i * 256;
        float v = (local[i] - mean) * inv * g[d] + beta[d];
        split_store(v, g_xn_h, g_xn_l, (long)blockIdx.x * DIM + d);
    }
}

// ---------------- fused flash attention (table RoPE + QK^T + softmax + AV) ----------------
#define FA_SQ  0
#define FA_KV  (64*68)
#define FA_S   (FA_KV + 32*68)
#define FA_TOT (FA_S + 64*352)

__global__ __launch_bounds__(256) void flash_attn_kernel(
        const float* __restrict__ qkv, u16* __restrict__ oh, u16* __restrict__ ol) {
    extern __shared__ float sm[];
    int tile = blockIdx.x;
    int bh = blockIdx.y;
    int h = bh % HEADS, b = bh / HEADS;
    int tid = threadIdx.x, lane = tid & 31, warp = tid >> 5;

    for (int i = tid; i < 64 * 64; i += 256) {
        int r = i >> 6, d = i & 63;
        int grow = tile * 64 + r;
        float v = 0.f;
        if (grow < NTOK) v = qkv[(long)(b * NTOK + grow) * 3072 + h * HD + d];
        sm[FA_SQ + r * 68 + d] = v;
    }
    __syncthreads();
    {
        float tmp[16];
#pragma unroll
        for (int t = 0; t < 16; t++) {
            int i = tid + t * 256;
            int r = i >> 6, d = i & 63;
            int grow = tile * 64 + r;
            float x = sm[FA_SQ + r * 68 + d];
            float pr = (d < 32) ? -sm[FA_SQ + r * 68 + 2 * d + 1] : sm[FA_SQ + r * 68 + 2 * (d - 32)];
            float c = g_ropec[grow * HD + d];
            float s = g_ropes[grow * HD + d];
            tmp[t] = x * c + pr * s;
        }
        __syncthreads();
#pragma unroll
        for (int t = 0; t < 16; t++) {
            int i = tid + t * 256;
            sm[FA_SQ + (i >> 6) * 68 + (i & 63)] = tmp[t];
        }
    }

    for (int c = 0; c < 11; c++) {
        __syncthreads();
        for (int i = tid; i < 32 * 64; i += 256) {
            int j = i >> 6, d = i & 63;
            int krow = c * 32 + j;
            float v = 0.f;
            if (krow < NTOK) v = qkv[(long)(b * NTOK + krow) * 3072 + DIM + h * HD + d];
            sm[FA_KV + j * 68 + d] = v;
        }
        __syncthreads();
        {
            float tmp[8];
#pragma unroll
            for (int t = 0; t < 8; t++) {
                int i = tid + t * 256;
                int j = i >> 6, d = i & 63;
                float x = sm[FA_KV + j * 68 + d];
                float pr = (d < 32) ? -sm[FA_KV + j * 68 + 2 * d + 1] : sm[FA_KV + j * 68 + 2 * (d - 32)];
                int krow = c * 32 + j;
                float cc = g_ropec[krow * HD + d];
                float ss = g_ropes[krow * HD + d];
                tmp[t] = x * cc + pr * ss;
            }
            __syncthreads();
#pragma unroll
            for (int t = 0; t < 8; t++) {
                int i = tid + t * 256;
                sm[FA_KV + (i >> 6) * 68 + (i & 63)] = tmp[t];
            }
        }
        __syncthreads();
        bool kvalid = (c * 32 + lane) < NTOK;
        const float* kr = &sm[FA_KV + lane * 68];
        float sacc[8];
#pragma unroll
        for (int r8 = 0; r8 < 8; r8++) sacc[r8] = 0.f;
#pragma unroll
        for (int dq = 0; dq < 16; dq++) {
            float4 kv = *(const float4*)(kr + dq * 4);
#pragma unroll
            for (int r8 = 0; r8 < 8; r8++) {
                float4 qv = *(const float4*)&sm[FA_SQ + (warp * 8 + r8) * 68 + dq * 4];
                sacc[r8] += qv.x * kv.x + qv.y * kv.y + qv.z * kv.z + qv.w * kv.w;
            }
        }
#pragma unroll
        for (int r8 = 0; r8 < 8; r8++) {
            int r = warp * 8 + r8;
            sm[FA_S + r * 352 + c * 32 + lane] = kvalid ? sacc[r8] * 0.125f : -1e30f;
        }
    }

    float invr[8];
#pragma unroll
    for (int r8 = 0; r8 < 8; r8++) {
        float* Sr = &sm[FA_S + (warp * 8 + r8) * 352];
        float mx = -1e30f;
#pragma unroll
        for (int k = 0; k < 11; k++) mx = fmaxf(mx, Sr[lane + k * 32]);
#pragma unroll
        for (int o = 16; o > 0; o >>= 1) mx = fmaxf(mx, __shfl_xor_sync(0xffffffffu, mx, o));
        float sum = 0.f;
#pragma unroll
        for (int k = 0; k < 11; k++) {
            float e = __expf(Sr[lane + k * 32] - mx);
            Sr[lane + k * 32] = e;
            sum += e;
        }
#pragma unroll
        for (int o = 16; o > 0; o >>= 1) sum += __shfl_xor_sync(0xffffffffu, sum, o);
        invr[r8] = 1.0f / sum;
    }

    float acc0[8], acc1[8];
#pragma unroll
    for (int r8 = 0; r8 < 8; r8++) { acc0[r8] = 0.f; acc1[r8] = 0.f; }
    for (int c = 0; c < 11; c++) {
        __syncthreads();
        for (int i = tid; i < 32 * 64; i += 256) {
            int j = i >> 6, d = i & 63;
            int vrow = c * 32 + j;
            float v = 0.f;
            if (vrow < NTOK) v = qkv[(long)(b * NTOK + vrow) * 3072 + 2 * DIM + h * HD + d];
            sm[FA_KV + j * 68 + d] = v;
        }
        __syncthreads();
#pragma unroll
        for (int jq = 0; jq < 8; jq++) {
            float v0[4], v1[4];
#pragma unroll
            for (int t = 0; t < 4; t++) {
                v0[t] = sm[FA_KV + (jq * 4 + t) * 68 + lane];
                v1[t] = sm[FA_KV + (jq * 4 + t) * 68 + lane + 32];
            }
#pragma unroll
            for (int r8 = 0; r8 < 8; r8++) {
                float4 p = *(const float4*)&sm[FA_S + (warp * 8 + r8) * 352 + c * 32 + jq * 4];
                acc0[r8] += p.x * v0[0] + p.y * v0[1] + p.z * v0[2] + p.w * v0[3];
                acc1[r8] += p.x * v1[0] + p.y * v1[1] + p.z * v1[2] + p.w * v1[3];
            }
        }
    }

#pragma unroll
    for (int r8 = 0; r8 < 8; r8++) {
        int grow = tile * 64 + warp * 8 + r8;
        if (grow >= NTOK) continue;
        long o = (long)(b * NTOK + grow) * DIM + h * HD + lane;
        split_store(acc0[r8] * invr[r8], oh, ol, o);
        split_store(acc1[r8] * invr[r8], oh, ol, o + 32);
    }
}

// ---------------- output unpatchify ----------------
__global__ void unpatch_kernel(float* __restrict__ out) {
    int idx = blockIdx.x * blockDim.x + threadIdx.x;
    if (idx >= BATCH * 3 * IMG * IMG) return;
    int c_img = idx % IMG;
    int r_img = (idx / IMG) % IMG;
    int ch = (idx / (IMG * IMG)) % 3;
    int b = idx / (3 * IMG * IMG);
    int hp = r_img / 16, pr = r_img % 16;
    int wp = c_img / 16, pc = c_img % 16;
    out[idx] = g_h[(long)(b * NPATCH + hp * 16 + wp) * PCH + ch * 256 + pr * 16 + pc];
}

// ---------------- host launch ----------------
static void* symaddr_raw(const void* sym) {
    void* p = nullptr;
    cudaGetSymbolAddress(&p, sym);
    return p;
}

#define SMEM128 (2 * (2 * 128 * 80 + 2 * 128 * 80))   // 81920
#define SMEM64  (2 * (2 * 128 * 80 + 2 * 64 * 80))    // 61440

extern "C" void kernel_launch(void* const* d_in, const int* in_sizes, int n_in,
                              void* d_out, int out_size) {
    const float* noisy    = (const float*)d_in[0];
    const int*   tokens   = (const int*)  d_in[1];
    const int*   tsteps   = (const int*)  d_in[2];
    const float* W_tok    = (const float*)d_in[3];
    const float* pos_text = (const float*)d_in[4];
    const float* W_patch  = (const float*)d_in[5];
    const float* pos_img  = (const float*)d_in[6];
    const float* cls_tok  = (const float*)d_in[7];
    const float* W_t1     = (const float*)d_in[8];
    const float* b_t1     = (const float*)d_in[9];
    const float* W_t2     = (const float*)d_in[10];
    const float* b_t2     = (const float*)d_in[11];
    const float* ln1_g    = (const float*)d_in[12];
    const float* ln1_b    = (const float*)d_in[13];
    const float* Wq       = (const float*)d_in[14];
    const float* Wk       = (const float*)d_in[15];
    const float* Wv       = (const float*)d_in[16];
    const float* Wo       = (const float*)d_in[17];
    const float* ln2_g    = (const float*)d_in[18];
    const float* ln2_b    = (const float*)d_in[19];
    const float* Wm1      = (const float*)d_in[20];
    const float* Wm2      = (const float*)d_in[21];
    const float* Wada     = (const float*)d_in[22];
    const float* b_ada    = (const float*)d_in[23];
    const float* fn_g     = (const float*)d_in[24];
    const float* fn_b     = (const float*)d_in[25];
    const float* W_final  = (const float*)d_in[26];
    const float* b_final  = (const float*)d_in[27];
    float* out = (float*)d_out;

    float* p_x    = (float*)symaddr_raw(g_x);
    float* p_qkv  = (float*)symaddr_raw(g_qkv);
    float* p_att  = (float*)symaddr_raw(g_att);
    float* p_h    = (float*)symaddr_raw(g_h);
    float* p_mod  = (float*)symaddr_raw(g_mod);
    u16* p_wh     = (u16*)symaddr_raw(g_w_h);
    u16* p_wl     = (u16*)symaddr_raw(g_w_l);
    u16* p_xnh    = (u16*)symaddr_raw(g_xn_h);
    u16* p_xnl    = (u16*)symaddr_raw(g_xn_l);
    u16* p_hh     = (u16*)symaddr_raw(g_hh);
    u16* p_hl     = (u16*)symaddr_raw(g_hl);
    u16* p_oh     = (u16*)symaddr_raw(g_o_h);
    u16* p_ol     = (u16*)symaddr_raw(g_o_l);
    u16* p_imh    = (u16*)symaddr_raw(g_im_h);
    u16* p_iml    = (u16*)symaddr_raw(g_im_l);

    static bool attr_set = false;
    if (!attr_set) {
        cudaFuncSetAttribute(mma_gemm2_kernel<128>, cudaFuncAttributeMaxDynamicSharedMemorySize, SMEM128);
        cudaFuncSetAttribute(mma_gemm2_kernel<64>, cudaFuncAttributeMaxDynamicSharedMemorySize, SMEM64);
        cudaFuncSetAttribute(flash_attn_kernel, cudaFuncAttributeMaxDynamicSharedMemorySize, FA_TOT * 4);
        attr_set = true;
    }

    im2col_kernel<<<(BATCH * NPATCH * PCH + 255) / 256, 256>>>(noisy);               // 0
    cvt_all_kernel<<<(WTOTAL / 4 + 511) / 512, 512>>>(W_patch, Wq, Wk, Wv, Wo, Wm1, Wm2, W_final); // 1
    ts_a_kernel<<<dim3(32, BATCH), 256>>>(tsteps, W_t1, b_t1);                        // 2
    // index 3: representative GEMM for ncu
    mma_gemm2_kernel<64><<<dim3(DIM / 64, 8), 256, SMEM64>>>(
        p_imh, p_iml, p_wh + OFF_PATCH, p_wl + OFF_PATCH,
        p_att, nullptr, nullptr, BATCH * NPATCH, DIM, PCH, nullptr, nullptr, 0, 0);   // 3
    rope_table_kernel<<<(NPAD * HD + 255) / 256, 256>>>();                            // 4
    ts_b_kernel<<<dim3(32, BATCH), 256>>>(W_t2, b_t2);                                // 5
    embed_text_cls_kernel<<<(BATCH * 65 * DIM + 255) / 256, 256>>>(tokens, W_tok, pos_text, cls_tok);
    add_posimg_kernel<<<(BATCH * NPATCH * DIM + 255) / 256, 256>>>(pos_img);

    int gy = (MROWS + 127) / 128;   // 11

    for (int l = 0; l < NLAYERS; l++) {
        long wqkv_o = OFF_QKV + (long)l * 3 * DD;
        long wo_o   = OFF_WO + (long)l * DD;
        long wm1_o  = OFF_WM1 + (long)l * MLPD * DIM;
        long wm2_o  = OFF_WM2 + (long)l * DIM * MLPD;
        const float* Wada_l = Wada + (long)l * 6 * DIM * DIM;
        const float* bada_l = b_ada + (long)l * 6 * DIM;

        ada_kernel<<<192, 256>>>(Wada_l, bada_l);

        ln_mod_kernel<<<MROWS, 256>>>(p_x, p_xnh, p_xnl, ln1_g + l * DIM, ln1_b + l * DIM,
                                      p_mod, 0, DIM);

        mma_gemm2_kernel<128><<<dim3(3 * DIM / 128, gy), 256, SMEM128>>>(
            p_xnh, p_xnl, p_wh + wqkv_o, p_wl + wqkv_o, p_qkv, nullptr, nullptr,
            MROWS, 3 * DIM, DIM, nullptr, nullptr, 0, 0);

        flash_attn_kernel<<<dim3(6, BATCH * HEADS), 256, FA_TOT * 4>>>(p_qkv, p_oh, p_ol);

        mma_gemm2_kernel<64><<<dim3(DIM / 64, gy), 256, SMEM64>>>(
            p_oh, p_ol, p_wh + wo_o, p_wl + wo_o, p_x, nullptr, nullptr,
            MROWS, DIM, DIM, nullptr, p_mod, 2 * DIM, 2);

        ln_mod_kernel<<<MROWS, 256>>>(p_x, p_xnh, p_xnl, ln2_g + l * DIM, ln2_b + l * DIM,
                                      p_mod, 3 * DIM, 4 * DIM);

        mma_gemm2_kernel<128><<<dim3(MLPD / 128, gy), 256, SMEM128>>>(
            p_xnh, p_xnl, p_wh + wm1_o, p_wl + wm1_o, nullptr, p_hh, p_hl,
            MROWS, MLPD, DIM, nullptr, nullptr, 0, 1);
        mma_gemm2_kernel<64><<<dim3(DIM / 64, gy), 256, SMEM64>>>(
            p_hh, p_hl, p_wh + wm2_o, p_wl + wm2_o, p_x, nullptr, nullptr,
            MROWS, DIM, MLPD, nullptr, p_mod, 5 * DIM, 2);
    }

    final_ln_kernel<<<BATCH * NPATCH, 256>>>(fn_g, fn_b);
    mma_gemm2_kernel<64><<<dim3(PCH / 64, 8), 256, SMEM64>>>(
        p_xnh, p_xnl, p_wh + OFF_FIN, p_wl + OFF_FIN, p_h, nullptr, nullptr,
        BATCH * NPATCH, PCH, DIM, b_final, nullptr, 0, 0);
    unpatch_kernel<<<(BATCH * 3 * IMG * IMG + 255) / 256, 256>>>(out);
}